// round 1
// baseline (speedup 1.0000x reference)
#include <cuda_runtime.h>
#include <math.h>

#define BATCH   2048
#define EMB     1024
#define MSIZE   100000
#define HEADS   8
#define HDIM    128
#define TOPK    10
#define SPLITS  20
#define SPLIT_SZ 5000
#define CAND    (SPLITS*TOPK)   // 200 candidates per query

// ---------------- device scratch (no allocations allowed) ----------------
__device__ float g_qp [BATCH*EMB];            // 8 MB   q projection
__device__ float g_kp [BATCH*TOPK*EMB];       // 80 MB  k projection (gathered)
__device__ float g_vp [BATCH*TOPK*EMB];       // 80 MB  v projection (gathered)
__device__ float g_ctx[BATCH*EMB];            // 8 MB   attention output
__device__ float g_cand_s[BATCH*CAND];
__device__ int   g_cand_i[BATCH*CAND];
__device__ int   g_topk [BATCH*TOPK];

// =====================================================================
// Kernel 1: fused sim (Q @ Mem^T) + exact per-split top-10
// Tile: 64 queries x 64 memories x K=1024 (BK=16), 256 thr, 4x4 micro
// grid = (SPLITS, BATCH/64)
// =====================================================================
__global__ void sim_topk_kernel(const float* __restrict__ query,
                                const float* __restrict__ memory)
{
    __shared__ float As[16][64];      // queries, k-major
    __shared__ float Bs[16][64];      // memories, k-major
    __shared__ float Cs[64][68];      // score tile (padded)
    __shared__ float Ls[64][TOPK];    // per-query top-10 scores
    __shared__ int   Li[64][TOPK];    // per-query top-10 indices

    const int t  = threadIdx.x;
    const int tx = t & 15;
    const int ty = t >> 4;
    const int qbase  = blockIdx.y * 64;
    const int mstart = blockIdx.x * SPLIT_SZ;
    const int mend   = min(mstart + SPLIT_SZ, MSIZE);

    if (t < 64) {
        #pragma unroll
        for (int i = 0; i < TOPK; i++) { Ls[t][i] = -1e30f; Li[t][i] = -1; }
    }
    __syncthreads();

    for (int mb = mstart; mb < mend; mb += 64) {
        float c[4][4];
        #pragma unroll
        for (int i = 0; i < 4; i++)
            #pragma unroll
            for (int j = 0; j < 4; j++) c[i][j] = 0.f;

        for (int kb = 0; kb < EMB; kb += 16) {
            #pragma unroll
            for (int l = 0; l < 4; l++) {
                int lin = t + l * 256;
                int kk  = lin & 15;
                int row = lin >> 4;
                As[kk][row] = query[(size_t)(qbase + row) * EMB + kb + kk];
                int mrow = mb + row;
                Bs[kk][row] = (mrow < mend)
                            ? memory[(size_t)mrow * EMB + kb + kk] : 0.f;
            }
            __syncthreads();
            #pragma unroll
            for (int kk = 0; kk < 16; kk++) {
                float4 a = *(const float4*)&As[kk][ty * 4];
                float4 b = *(const float4*)&Bs[kk][tx * 4];
                float av[4] = {a.x, a.y, a.z, a.w};
                float bv[4] = {b.x, b.y, b.z, b.w};
                #pragma unroll
                for (int i = 0; i < 4; i++)
                    #pragma unroll
                    for (int j = 0; j < 4; j++)
                        c[i][j] = fmaf(av[i], bv[j], c[i][j]);
            }
            __syncthreads();
        }

        // stage scores to smem, then 64 threads do the top-k scan
        #pragma unroll
        for (int i = 0; i < 4; i++)
            #pragma unroll
            for (int j = 0; j < 4; j++)
                Cs[ty * 4 + i][tx * 4 + j] = c[i][j];
        __syncthreads();

        if (t < 64) {
            int nvalid = min(64, mend - mb);
            for (int j = 0; j < nvalid; j++) {
                float s = Cs[t][j];
                if (s > Ls[t][TOPK - 1]) {
                    int p = TOPK - 1;
                    while (p > 0 && Ls[t][p - 1] < s) {
                        Ls[t][p] = Ls[t][p - 1];
                        Li[t][p] = Li[t][p - 1];
                        p--;
                    }
                    Ls[t][p] = s;
                    Li[t][p] = mb + j;
                }
            }
        }
        __syncthreads();
    }

    if (t < 64) {
        int q = qbase + t;
        #pragma unroll
        for (int i = 0; i < TOPK; i++) {
            g_cand_s[(size_t)q * CAND + blockIdx.x * TOPK + i] = Ls[t][i];
            g_cand_i[(size_t)q * CAND + blockIdx.x * TOPK + i] = Li[t][i];
        }
    }
}

// =====================================================================
// Kernel 2: merge 200 per-split candidates -> global top-10 (1 warp/query)
// =====================================================================
__global__ void merge_topk_kernel()
{
    int gw   = (blockIdx.x * blockDim.x + threadIdx.x) >> 5;
    int lane = threadIdx.x & 31;
    if (gw >= BATCH) return;

    float s[7]; int id[7];
    #pragma unroll
    for (int l = 0; l < 7; l++) {
        int ci = lane + l * 32;
        if (ci < CAND) {
            s[l]  = g_cand_s[(size_t)gw * CAND + ci];
            id[l] = g_cand_i[(size_t)gw * CAND + ci];
        } else { s[l] = -1e30f; id[l] = 0x7fffffff; }
    }

    for (int sel = 0; sel < TOPK; sel++) {
        float bs = -1e30f; int bi = 0x7fffffff;
        #pragma unroll
        for (int l = 0; l < 7; l++)
            if (s[l] > bs || (s[l] == bs && id[l] < bi)) { bs = s[l]; bi = id[l]; }
        #pragma unroll
        for (int off = 16; off > 0; off >>= 1) {
            float os = __shfl_down_sync(0xffffffffu, bs, off);
            int   oi = __shfl_down_sync(0xffffffffu, bi, off);
            if (os > bs || (os == bs && oi < bi)) { bs = os; bi = oi; }
        }
        bi = __shfl_sync(0xffffffffu, bi, 0);
        if (lane == 0) g_topk[gw * TOPK + sel] = bi;
        #pragma unroll
        for (int l = 0; l < 7; l++)
            if (id[l] == bi) s[l] = -1e30f;
    }
}

// =====================================================================
// Kernel 3: generic C[M,1024] = A @ B^T + bias, optional row gather on A
// Tile 64x64x16, 256 thr, 4x4 micro. grid=(16, M/64)
// =====================================================================
__global__ void gemm_nt_kernel(const float* __restrict__ Asrc,
                               const float* __restrict__ B,
                               const float* __restrict__ bias,
                               float* __restrict__ C,
                               const int* __restrict__ gather)
{
    __shared__ float As[16][64];
    __shared__ float Bs[16][64];
    __shared__ int   rowIdx[64];

    const int t  = threadIdx.x;
    const int tx = t & 15;
    const int ty = t >> 4;
    const int rbase = blockIdx.y * 64;
    const int cbase = blockIdx.x * 64;

    if (t < 64) rowIdx[t] = gather ? gather[rbase + t] : (rbase + t);
    __syncthreads();

    float c[4][4];
    #pragma unroll
    for (int i = 0; i < 4; i++)
        #pragma unroll
        for (int j = 0; j < 4; j++) c[i][j] = 0.f;

    for (int kb = 0; kb < EMB; kb += 16) {
        #pragma unroll
        for (int l = 0; l < 4; l++) {
            int lin = t + l * 256;
            int kk  = lin & 15;
            int row = lin >> 4;
            As[kk][row] = Asrc[(size_t)rowIdx[row] * EMB + kb + kk];
            Bs[kk][row] = B[(size_t)(cbase + row) * EMB + kb + kk];
        }
        __syncthreads();
        #pragma unroll
        for (int kk = 0; kk < 16; kk++) {
            float4 a = *(const float4*)&As[kk][ty * 4];
            float4 b = *(const float4*)&Bs[kk][tx * 4];
            float av[4] = {a.x, a.y, a.z, a.w};
            float bv[4] = {b.x, b.y, b.z, b.w};
            #pragma unroll
            for (int i = 0; i < 4; i++)
                #pragma unroll
                for (int j = 0; j < 4; j++)
                    c[i][j] = fmaf(av[i], bv[j], c[i][j]);
        }
        __syncthreads();
    }

    #pragma unroll
    for (int i = 0; i < 4; i++)
        #pragma unroll
        for (int j = 0; j < 4; j++)
            C[(size_t)(rbase + ty * 4 + i) * EMB + cbase + tx * 4 + j] =
                c[i][j] + bias[cbase + tx * 4 + j];
}

// =====================================================================
// Kernel 4: attention over 10 retrieved memories, 1 warp per (b, h)
// =====================================================================
__global__ void attention_kernel()
{
    int w    = threadIdx.x >> 5;
    int lane = threadIdx.x & 31;
    int unit = blockIdx.x * 8 + w;     // blockDim = 256 -> 8 warps
    int b = unit >> 3;
    int h = unit & 7;

    const float* q = g_qp + (size_t)b * EMB + h * HDIM;
    float q4[4];
    #pragma unroll
    for (int i = 0; i < 4; i++) q4[i] = q[lane * 4 + i];

    const float scale = 0.08838834764831845f;  // 1/sqrt(128)
    float sc[TOPK];
    #pragma unroll
    for (int k = 0; k < TOPK; k++) {
        const float* kr = g_kp + (size_t)(b * TOPK + k) * EMB + h * HDIM;
        float p = 0.f;
        #pragma unroll
        for (int i = 0; i < 4; i++) p = fmaf(q4[i], kr[lane * 4 + i], p);
        #pragma unroll
        for (int off = 16; off > 0; off >>= 1)
            p += __shfl_xor_sync(0xffffffffu, p, off);
        sc[k] = p * scale;
    }

    float mx = sc[0];
    #pragma unroll
    for (int k = 1; k < TOPK; k++) mx = fmaxf(mx, sc[k]);
    float e[TOPK], sum = 0.f;
    #pragma unroll
    for (int k = 0; k < TOPK; k++) { e[k] = expf(sc[k] - mx); sum += e[k]; }
    float inv = 1.f / sum;

    float acc[4] = {0.f, 0.f, 0.f, 0.f};
    #pragma unroll
    for (int k = 0; k < TOPK; k++) {
        float a = e[k] * inv;
        const float* vr = g_vp + (size_t)(b * TOPK + k) * EMB + h * HDIM;
        #pragma unroll
        for (int i = 0; i < 4; i++) acc[i] = fmaf(a, vr[lane * 4 + i], acc[i]);
    }
    #pragma unroll
    for (int i = 0; i < 4; i++)
        g_ctx[(size_t)b * EMB + h * HDIM + lane * 4 + i] = acc[i];
}

// =====================================================================
extern "C" void kernel_launch(void* const* d_in, const int* in_sizes, int n_in,
                              void* d_out, int out_size)
{
    const float* query  = (const float*)d_in[0];
    const float* memory = (const float*)d_in[1];
    const float* w_q    = (const float*)d_in[2];
    const float* w_k    = (const float*)d_in[3];
    const float* w_v    = (const float*)d_in[4];
    const float* b_q    = (const float*)d_in[5];
    const float* b_k    = (const float*)d_in[6];
    const float* b_v    = (const float*)d_in[7];
    const float* w_o    = (const float*)d_in[8];
    const float* b_o    = (const float*)d_in[9];
    float* out = (float*)d_out;

    float *qp, *kp, *vp, *ctx; int *tk;
    cudaGetSymbolAddress((void**)&qp,  g_qp);
    cudaGetSymbolAddress((void**)&kp,  g_kp);
    cudaGetSymbolAddress((void**)&vp,  g_vp);
    cudaGetSymbolAddress((void**)&ctx, g_ctx);
    cudaGetSymbolAddress((void**)&tk,  g_topk);

    // 1) similarity + per-split exact top-10
    sim_topk_kernel<<<dim3(SPLITS, BATCH / 64), 256>>>(query, memory);
    // 2) merge candidates -> global top-10
    merge_topk_kernel<<<BATCH / 8, 256>>>();
    // 3) q projection
    gemm_nt_kernel<<<dim3(16, BATCH / 64), 256>>>(query, w_q, b_q, qp, nullptr);
    // 4) gathered k / v projections
    gemm_nt_kernel<<<dim3(16, BATCH * TOPK / 64), 256>>>(memory, w_k, b_k, kp, tk);
    gemm_nt_kernel<<<dim3(16, BATCH * TOPK / 64), 256>>>(memory, w_v, b_v, vp, tk);
    // 5) attention
    attention_kernel<<<BATCH * HEADS / 8, 256>>>();
    // 6) output projection -> d_out
    gemm_nt_kernel<<<dim3(16, BATCH / 64), 256>>>(ctx, w_o, b_o, out, nullptr);
}

// round 3
// speedup vs baseline: 6.0138x; 6.0138x over previous
#include <cuda_runtime.h>
#include <cuda_bf16.h>
#include <math.h>

#define BATCH   2048
#define EMB     1024
#define MSIZE   100000
#define HEADS   8
#define HDIM    128
#define TOPK    10
#define SPLITS  16
#define SPLIT_SZ 6250           // 16 * 6250 = 100000
#define CAND    (SPLITS*TOPK)   // 160 candidates per query

// ---------------- device scratch ----------------
__device__ __nv_bfloat16 g_mem_bf[MSIZE*EMB];   // 200 MB
__device__ __nv_bfloat16 g_q_bf  [BATCH*EMB];   // 4 MB
__device__ float g_qp [BATCH*EMB];              // 8 MB
__device__ float g_T  [BATCH*HEADS*EMB];        // 64 MB  (qp_h @ W_k_h)
__device__ float g_wm [BATCH*HEADS*EMB];        // 64 MB  (attn-weighted memory)
__device__ float g_ctx[BATCH*EMB];              // 8 MB
__device__ float g_cand_s[BATCH*CAND];
__device__ int   g_cand_i[BATCH*CAND];
__device__ int   g_topk [BATCH*TOPK];

// =====================================================================
// fp32 -> bf16 conversion (vectorized x4)
// =====================================================================
__global__ void to_bf16_kernel(const float* __restrict__ src,
                               __nv_bfloat16* __restrict__ dst, int n4)
{
    int i = blockIdx.x * blockDim.x + threadIdx.x;
    if (i >= n4) return;
    float4 v = ((const float4*)src)[i];
    __nv_bfloat16 o[4];
    o[0] = __float2bfloat16(v.x); o[1] = __float2bfloat16(v.y);
    o[2] = __float2bfloat16(v.z); o[3] = __float2bfloat16(v.w);
    ((uint2*)dst)[i] = *(uint2*)o;
}

// =====================================================================
// MMA helpers
// =====================================================================
__device__ __forceinline__ void ldsm4(unsigned &r0, unsigned &r1,
                                      unsigned &r2, unsigned &r3, unsigned addr)
{
    asm volatile("ldmatrix.sync.aligned.m8n8.x4.shared.b16 {%0,%1,%2,%3}, [%4];"
                 : "=r"(r0), "=r"(r1), "=r"(r2), "=r"(r3) : "r"(addr));
}
__device__ __forceinline__ void mma_bf16(float* c,
    unsigned a0, unsigned a1, unsigned a2, unsigned a3,
    unsigned b0, unsigned b1)
{
    asm volatile(
        "mma.sync.aligned.m16n8k16.row.col.f32.bf16.bf16.f32 "
        "{%0,%1,%2,%3}, {%4,%5,%6,%7}, {%8,%9}, {%0,%1,%2,%3};"
        : "+f"(c[0]), "+f"(c[1]), "+f"(c[2]), "+f"(c[3])
        : "r"(a0), "r"(a1), "r"(a2), "r"(a3), "r"(b0), "r"(b1));
}

// =====================================================================
// Kernel 1: coarse sim = Qbf16 @ Membf16^T via tensor cores,
// fused per-split top-10 CANDIDATE generation (rescored exactly later).
// CTA tile: 64 q x 128 m, K-chunk 32, 8 warps (2x4), warp tile 32x32
// grid = (SPLITS, BATCH/64)
// =====================================================================
__global__ void sim_topk_mma(void)
{
    __shared__ __align__(16) unsigned char u_smem[64 * 133 * 4]; // 34048 B
    __shared__ float Ls[64][TOPK];
    __shared__ int   Li[64][TOPK];
    __nv_bfloat16 (*As)[40] = (__nv_bfloat16(*)[40])u_smem;            // 64 x 40
    __nv_bfloat16 (*Bs)[40] = (__nv_bfloat16(*)[40])(u_smem + 5120);   // 128 x 40
    float (*Cs)[133] = (float(*)[133])u_smem;                          // 64 x 133

    const int t    = threadIdx.x;
    const int lane = t & 31;
    const int warp = t >> 5;
    const int wq   = warp >> 2;   // 0..1 : q strip
    const int wm_  = warp & 3;    // 0..3 : m strip
    const int qbase  = blockIdx.y * 64;
    const int mstart = blockIdx.x * SPLIT_SZ;
    const int mend   = min(mstart + SPLIT_SZ, MSIZE);

    if (t < 64) {
        #pragma unroll
        for (int i = 0; i < TOPK; i++) { Ls[t][i] = -1e30f; Li[t][i] = -1; }
    }
    __syncthreads();

    unsigned sbase = (unsigned)__cvta_generic_to_shared(u_smem);
    unsigned aAddr = sbase + (unsigned)((wq*32 + (lane & 15)) * 80 + ((lane >> 4) * 16));
    int mi = lane >> 3;
    unsigned bAddr = sbase + 5120u +
        (unsigned)((wm_*32 + ((mi >> 1) * 8) + (lane & 7)) * 80 + (mi & 1) * 16);

    for (int mb = mstart; mb < mend; mb += 128) {
        float c[2][4][4];
        #pragma unroll
        for (int a = 0; a < 2; a++)
            #pragma unroll
            for (int b = 0; b < 4; b++)
                #pragma unroll
                for (int i = 0; i < 4; i++) c[a][b][i] = 0.f;

        for (int kb = 0; kb < EMB; kb += 32) {
            {
                int ar = t >> 2, ak = (t & 3) * 8;
                *(uint4*)&As[ar][ak] =
                    *(const uint4*)&g_q_bf[(size_t)(qbase + ar) * EMB + kb + ak];
                #pragma unroll
                for (int i = 0; i < 2; i++) {
                    int lin = t + i * 256;
                    int br = lin >> 2, bk = (lin & 3) * 8;
                    uint4 v = make_uint4(0u, 0u, 0u, 0u);
                    if (mb + br < mend)
                        v = *(const uint4*)&g_mem_bf[(size_t)(mb + br) * EMB + kb + bk];
                    *(uint4*)&Bs[br][bk] = v;
                }
            }
            __syncthreads();

            #pragma unroll
            for (int kk = 0; kk < 2; kk++) {
                unsigned a[2][4];
                #pragma unroll
                for (int aq = 0; aq < 2; aq++)
                    ldsm4(a[aq][0], a[aq][1], a[aq][2], a[aq][3],
                          aAddr + aq * (16 * 80) + kk * 32);
                unsigned b[4][2];
                #pragma unroll
                for (int p = 0; p < 2; p++) {
                    unsigned r0, r1, r2, r3;
                    ldsm4(r0, r1, r2, r3, bAddr + p * (16 * 80) + kk * 32);
                    b[p*2][0] = r0; b[p*2][1] = r1;
                    b[p*2+1][0] = r2; b[p*2+1][1] = r3;
                }
                #pragma unroll
                for (int aq = 0; aq < 2; aq++)
                    #pragma unroll
                    for (int bn = 0; bn < 4; bn++)
                        mma_bf16(c[aq][bn], a[aq][0], a[aq][1], a[aq][2], a[aq][3],
                                 b[bn][0], b[bn][1]);
            }
            __syncthreads();
        }

        #pragma unroll
        for (int aq = 0; aq < 2; aq++)
            #pragma unroll
            for (int bn = 0; bn < 4; bn++) {
                int r0 = wq*32 + aq*16 + (lane >> 2);
                int c0 = wm_*32 + bn*8 + (lane & 3) * 2;
                Cs[r0][c0]       = c[aq][bn][0];
                Cs[r0][c0 + 1]   = c[aq][bn][1];
                Cs[r0+8][c0]     = c[aq][bn][2];
                Cs[r0+8][c0 + 1] = c[aq][bn][3];
            }
        __syncthreads();

        if (t < 64) {
            int nv = min(128, mend - mb);
            for (int j = 0; j < nv; j++) {
                float s = Cs[t][j];
                if (s > Ls[t][TOPK - 1]) {
                    int p = TOPK - 1;
                    while (p > 0 && Ls[t][p - 1] < s) {
                        Ls[t][p] = Ls[t][p - 1];
                        Li[t][p] = Li[t][p - 1];
                        p--;
                    }
                    Ls[t][p] = s;
                    Li[t][p] = mb + j;
                }
            }
        }
        __syncthreads();
    }

    if (t < 64) {
        int q = qbase + t;
        #pragma unroll
        for (int i = 0; i < TOPK; i++)
            g_cand_i[(size_t)q * CAND + blockIdx.x * TOPK + i] = Li[t][i];
    }
}

// =====================================================================
// Kernel 2: EXACT fp32 rescore of the 160 candidates per query.
// 1 CTA (256 thr, 8 warps) per query; each warp handles 20 candidates.
// =====================================================================
__global__ void rescore_kernel(const float* __restrict__ query,
                               const float* __restrict__ memory)
{
    __shared__ float qs[EMB];
    const int b    = blockIdx.x;
    const int t    = threadIdx.x;
    const int lane = t & 31;
    const int warp = t >> 5;

    for (int i = t; i < EMB / 4; i += 256)
        *(float4*)&qs[i * 4] = *(const float4*)&query[(size_t)b * EMB + i * 4];
    __syncthreads();

    for (int ci = warp; ci < CAND; ci += 8) {
        int midx = g_cand_i[(size_t)b * CAND + ci];
        const float* m = memory + (size_t)midx * EMB;
        float p = 0.f;
        #pragma unroll
        for (int i = 0; i < EMB / 128; i++) {       // 8 float4 per lane
            float4 mv = *(const float4*)&m[(lane + i * 32) * 4];
            float4 qv = *(const float4*)&qs[(lane + i * 32) * 4];
            p = fmaf(qv.x, mv.x, p);
            p = fmaf(qv.y, mv.y, p);
            p = fmaf(qv.z, mv.z, p);
            p = fmaf(qv.w, mv.w, p);
        }
        #pragma unroll
        for (int off = 16; off > 0; off >>= 1)
            p += __shfl_xor_sync(0xffffffffu, p, off);
        if (lane == 0) g_cand_s[(size_t)b * CAND + ci] = p;
    }
}

// =====================================================================
// Kernel 3: exact top-10 of the 160 exact scores (1 warp/query)
// =====================================================================
__global__ void merge_topk_kernel()
{
    int gw   = (blockIdx.x * blockDim.x + threadIdx.x) >> 5;
    int lane = threadIdx.x & 31;
    if (gw >= BATCH) return;

    float s[5]; int id[5];
    #pragma unroll
    for (int l = 0; l < 5; l++) {
        int ci = lane + l * 32;
        s[l]  = g_cand_s[(size_t)gw * CAND + ci];
        id[l] = g_cand_i[(size_t)gw * CAND + ci];
    }

    for (int sel = 0; sel < TOPK; sel++) {
        float bs = -1e30f; int bi = 0x7fffffff;
        #pragma unroll
        for (int l = 0; l < 5; l++)
            if (s[l] > bs || (s[l] == bs && id[l] < bi)) { bs = s[l]; bi = id[l]; }
        #pragma unroll
        for (int off = 16; off > 0; off >>= 1) {
            float os = __shfl_down_sync(0xffffffffu, bs, off);
            int   oi = __shfl_down_sync(0xffffffffu, bi, off);
            if (os > bs || (os == bs && oi < bi)) { bs = os; bi = oi; }
        }
        bi = __shfl_sync(0xffffffffu, bi, 0);
        if (lane == 0) g_topk[gw * TOPK + sel] = bi;
        #pragma unroll
        for (int l = 0; l < 5; l++)
            if (id[l] == bi) s[l] = -1e30f;
    }
}

// =====================================================================
// Kernel 4: generic fp32 NT GEMM  C = A @ B^T + bias, K=1024, per-head strides
// tile 64x64x16, 256 thr, 4x4 micro. grid=(N/64, M/64, nheads)
// =====================================================================
__global__ void gemm_nt_gen(const float* __restrict__ A, int lda, long hsA,
                            const float* __restrict__ B, long hsB,
                            const float* __restrict__ bias, int hsBias,
                            float* __restrict__ C, int ldc, long hsC)
{
    __shared__ float As[16][64];
    __shared__ float Bs[16][64];

    const float* Az = A + (size_t)blockIdx.z * hsA;
    const float* Bz = B + (size_t)blockIdx.z * hsB;
    const float* bz = bias + (size_t)blockIdx.z * hsBias;
    float*       Cz = C + (size_t)blockIdx.z * hsC;

    const int t  = threadIdx.x;
    const int tx = t & 15;
    const int ty = t >> 4;
    const int rbase = blockIdx.y * 64;
    const int cbase = blockIdx.x * 64;

    float c[4][4];
    #pragma unroll
    for (int i = 0; i < 4; i++)
        #pragma unroll
        for (int j = 0; j < 4; j++) c[i][j] = 0.f;

    for (int kb = 0; kb < EMB; kb += 16) {
        #pragma unroll
        for (int l = 0; l < 4; l++) {
            int lin = t + l * 256;
            int kk  = lin & 15;
            int row = lin >> 4;
            As[kk][row] = Az[(size_t)(rbase + row) * lda + kb + kk];
            Bs[kk][row] = Bz[(size_t)(cbase + row) * EMB + kb + kk];
        }
        __syncthreads();
        #pragma unroll
        for (int kk = 0; kk < 16; kk++) {
            float4 a = *(const float4*)&As[kk][ty * 4];
            float4 b = *(const float4*)&Bs[kk][tx * 4];
            float av[4] = {a.x, a.y, a.z, a.w};
            float bv[4] = {b.x, b.y, b.z, b.w};
            #pragma unroll
            for (int i = 0; i < 4; i++)
                #pragma unroll
                for (int j = 0; j < 4; j++)
                    c[i][j] = fmaf(av[i], bv[j], c[i][j]);
        }
        __syncthreads();
    }

    #pragma unroll
    for (int i = 0; i < 4; i++)
        #pragma unroll
        for (int j = 0; j < 4; j++)
            Cz[(size_t)(rbase + ty * 4 + i) * ldc + cbase + tx * 4 + j] =
                c[i][j] + bz[cbase + tx * 4 + j];
}

// =====================================================================
// Kernel 5: T[b,h,:] = qp[b, h*128:(h+1)*128] @ w_k[h*128:(h+1)*128, :]
// NN GEMM, K=128. tile 64x64x16. grid=(16, 32, 8)
// =====================================================================
__global__ void gemm_nn_T(const float* __restrict__ qp,
                          const float* __restrict__ wk,
                          float* __restrict__ T)
{
    __shared__ float As[16][64];
    __shared__ float Bs[16][64];

    const int h = blockIdx.z;
    const int t  = threadIdx.x;
    const int tx = t & 15;
    const int ty = t >> 4;
    const int rbase = blockIdx.y * 64;
    const int cbase = blockIdx.x * 64;
    const float* Bz = wk + (size_t)h * HDIM * EMB;

    float c[4][4];
    #pragma unroll
    for (int i = 0; i < 4; i++)
        #pragma unroll
        for (int j = 0; j < 4; j++) c[i][j] = 0.f;

    for (int kb = 0; kb < HDIM; kb += 16) {
        #pragma unroll
        for (int l = 0; l < 4; l++) {
            int lin = t + l * 256;
            {
                int kk  = lin & 15;
                int row = lin >> 4;
                As[kk][row] = qp[(size_t)(rbase + row) * EMB + h * HDIM + kb + kk];
            }
            {
                int col = lin & 63;
                int kk  = lin >> 6;
                Bs[kk][col] = Bz[(size_t)(kb + kk) * EMB + cbase + col];
            }
        }
        __syncthreads();
        #pragma unroll
        for (int kk = 0; kk < 16; kk++) {
            float4 a = *(const float4*)&As[kk][ty * 4];
            float4 b = *(const float4*)&Bs[kk][tx * 4];
            float av[4] = {a.x, a.y, a.z, a.w};
            float bv[4] = {b.x, b.y, b.z, b.w};
            #pragma unroll
            for (int i = 0; i < 4; i++)
                #pragma unroll
                for (int j = 0; j < 4; j++)
                    c[i][j] = fmaf(av[i], bv[j], c[i][j]);
        }
        __syncthreads();
    }

    #pragma unroll
    for (int i = 0; i < 4; i++)
        #pragma unroll
        for (int j = 0; j < 4; j++)
            T[(size_t)(rbase + ty * 4 + i) * (HEADS * EMB) + h * EMB +
              cbase + tx * 4 + j] = c[i][j];
}

// =====================================================================
// Kernel 6: attention. 1 CTA per batch row, 8 warps = 8 heads.
// =====================================================================
__global__ void attention2(const float* __restrict__ mem,
                           const float* __restrict__ b_k)
{
    __shared__ float Ms[TOPK][EMB];   // 40 KB
    __shared__ int   idxs[TOPK];

    const int b = blockIdx.x;
    const int t = threadIdx.x;
    const int lane = t & 31;
    const int h = t >> 5;

    if (t < TOPK) idxs[t] = g_topk[b * TOPK + t];
    __syncthreads();

    for (int i = t; i < TOPK * (EMB / 4); i += 256) {
        int k  = i >> 8;
        int e4 = i & 255;
        *(float4*)&Ms[k][e4 * 4] =
            *(const float4*)&mem[(size_t)idxs[k] * EMB + e4 * 4];
    }
    __syncthreads();

    float Tr[32];
    const float* Tp = g_T + (size_t)b * HEADS * EMB + h * EMB;
    #pragma unroll
    for (int i = 0; i < 32; i++) Tr[i] = Tp[lane + i * 32];

    float cb = 0.f;
    const float* qpp = g_qp + (size_t)b * EMB + h * HDIM;
    const float* bkp = b_k + h * HDIM;
    #pragma unroll
    for (int j = 0; j < 4; j++) cb = fmaf(qpp[lane*4+j], bkp[lane*4+j], cb);
    #pragma unroll
    for (int off = 16; off > 0; off >>= 1)
        cb += __shfl_xor_sync(0xffffffffu, cb, off);

    const float scale = 0.08838834764831845f;  // 1/sqrt(128)
    float sc[TOPK];
    #pragma unroll
    for (int k = 0; k < TOPK; k++) {
        float p = 0.f;
        #pragma unroll
        for (int i = 0; i < 32; i++) p = fmaf(Tr[i], Ms[k][lane + i * 32], p);
        #pragma unroll
        for (int off = 16; off > 0; off >>= 1)
            p += __shfl_xor_sync(0xffffffffu, p, off);
        sc[k] = (p + cb) * scale;
    }

    float mx = sc[0];
    #pragma unroll
    for (int k = 1; k < TOPK; k++) mx = fmaxf(mx, sc[k]);
    float w[TOPK], sum = 0.f;
    #pragma unroll
    for (int k = 0; k < TOPK; k++) { w[k] = expf(sc[k] - mx); sum += w[k]; }
    float inv = 1.f / sum;
    #pragma unroll
    for (int k = 0; k < TOPK; k++) w[k] *= inv;

    float* wmp = g_wm + (size_t)b * HEADS * EMB + h * EMB;
    #pragma unroll
    for (int i = 0; i < 32; i++) {
        int e = lane + i * 32;
        float a = 0.f;
        #pragma unroll
        for (int k = 0; k < TOPK; k++) a = fmaf(w[k], Ms[k][e], a);
        wmp[e] = a;
    }
}

// =====================================================================
extern "C" void kernel_launch(void* const* d_in, const int* in_sizes, int n_in,
                              void* d_out, int out_size)
{
    const float* query  = (const float*)d_in[0];
    const float* memory = (const float*)d_in[1];
    const float* w_q    = (const float*)d_in[2];
    const float* w_k    = (const float*)d_in[3];
    const float* w_v    = (const float*)d_in[4];
    const float* b_q    = (const float*)d_in[5];
    const float* b_k    = (const float*)d_in[6];
    const float* b_v    = (const float*)d_in[7];
    const float* w_o    = (const float*)d_in[8];
    const float* b_o    = (const float*)d_in[9];
    float* out = (float*)d_out;

    __nv_bfloat16 *mbf, *qbf;
    float *qp, *T, *wm, *ctx;
    cudaGetSymbolAddress((void**)&mbf, g_mem_bf);
    cudaGetSymbolAddress((void**)&qbf, g_q_bf);
    cudaGetSymbolAddress((void**)&qp,  g_qp);
    cudaGetSymbolAddress((void**)&T,   g_T);
    cudaGetSymbolAddress((void**)&wm,  g_wm);
    cudaGetSymbolAddress((void**)&ctx, g_ctx);

    // 1) bf16 conversions (candidate-generation path only)
    to_bf16_kernel<<<(MSIZE*EMB/4 + 255)/256, 256>>>(memory, mbf, MSIZE*EMB/4);
    to_bf16_kernel<<<(BATCH*EMB/4 + 255)/256, 256>>>(query,  qbf, BATCH*EMB/4);

    // 2) tensor-core coarse similarity -> 160 candidates/query
    sim_topk_mma<<<dim3(SPLITS, BATCH/64), 256>>>();

    // 3) exact fp32 rescore of candidates
    rescore_kernel<<<BATCH, 256>>>(query, memory);

    // 4) exact top-10
    merge_topk_kernel<<<BATCH/8, 256>>>();

    // 5) q projection: qp = query @ w_q^T + b_q
    gemm_nt_gen<<<dim3(16, 32, 1), 256>>>(query, EMB, 0, w_q, 0, b_q, 0, qp, EMB, 0);

    // 6) T[b,h,:] = qp_h @ w_k_h   (absorbs k-projection)
    gemm_nn_T<<<dim3(16, 32, 8), 256>>>(qp, w_k, T);

    // 7) attention: scores, softmax, weighted memory sum
    attention2<<<BATCH, 256>>>(memory, b_k);

    // 8) ctx_h = wm_h @ w_v_h^T + b_v_h   (absorbs v-projection)
    gemm_nt_gen<<<dim3(2, 32, 8), 256>>>(wm, HEADS*EMB, EMB,
                                         w_v, (long)HDIM*EMB,
                                         b_v, HDIM,
                                         ctx, EMB, HDIM);

    // 9) out = ctx @ w_o^T + b_o
    gemm_nt_gen<<<dim3(16, 32, 1), 256>>>(ctx, EMB, 0, w_o, 0, b_o, 0, out, EMB, 0);
}

// round 4
// speedup vs baseline: 6.5139x; 1.0832x over previous
#include <cuda_runtime.h>
#include <cuda_bf16.h>
#include <math.h>
#include <stdint.h>

#define BATCH   2048
#define EMB     1024
#define MSIZE   100000
#define HEADS   8
#define HDIM    128
#define TOPK    10
#define SPLITS  16
#define SPLIT_SZ 6250           // 16 * 6250 = 100000
#define CAND    (SPLITS*TOPK)   // 160 candidates per query

// ---- sim kernel smem layout (dynamic) ----
#define SA_STRIDE_B 2064                    // 1032 bf16 per row (pad 8) -> conflict-free ldmatrix
#define SA_BYTES    (64 * SA_STRIDE_B)      // 132096
#define SB_STRIDE_B 144                     // 72 bf16 per row (pad 8)
#define SB_BYTES    (128 * SB_STRIDE_B)     // 18432 per buffer
#define NBUF        3
#define CS_OFF      (SA_BYTES + NBUF * SB_BYTES)          // 187392
#define CS_STRIDE   132
#define SIM_DSMEM   (CS_OFF + 64 * CS_STRIDE * 4)         // 221184

// ---------------- device scratch ----------------
__device__ __nv_bfloat16 g_mem_bf[MSIZE*EMB];   // 200 MB
__device__ __nv_bfloat16 g_q_bf  [BATCH*EMB];   // 4 MB
__device__ float g_qp [BATCH*EMB];              // 8 MB
__device__ float g_T  [BATCH*HEADS*EMB];        // 64 MB  (qp_h @ W_k_h)
__device__ float g_wm [BATCH*HEADS*EMB];        // 64 MB  (attn-weighted memory)
__device__ float g_ctx[BATCH*EMB];              // 8 MB
__device__ float g_cand_s[BATCH*CAND];
__device__ int   g_cand_i[BATCH*CAND];
__device__ int   g_topk [BATCH*TOPK];

// =====================================================================
// fp32 -> bf16 conversion (vectorized x4)
// =====================================================================
__global__ void to_bf16_kernel(const float* __restrict__ src,
                               __nv_bfloat16* __restrict__ dst, int n4)
{
    int i = blockIdx.x * blockDim.x + threadIdx.x;
    if (i >= n4) return;
    float4 v = ((const float4*)src)[i];
    __nv_bfloat16 o[4];
    o[0] = __float2bfloat16(v.x); o[1] = __float2bfloat16(v.y);
    o[2] = __float2bfloat16(v.z); o[3] = __float2bfloat16(v.w);
    ((uint2*)dst)[i] = *(uint2*)o;
}

// =====================================================================
// MMA / async-copy helpers
// =====================================================================
__device__ __forceinline__ void ldsm4(unsigned &r0, unsigned &r1,
                                      unsigned &r2, unsigned &r3, unsigned addr)
{
    asm volatile("ldmatrix.sync.aligned.m8n8.x4.shared.b16 {%0,%1,%2,%3}, [%4];"
                 : "=r"(r0), "=r"(r1), "=r"(r2), "=r"(r3) : "r"(addr));
}
__device__ __forceinline__ void mma_bf16(float* c,
    unsigned a0, unsigned a1, unsigned a2, unsigned a3,
    unsigned b0, unsigned b1)
{
    asm volatile(
        "mma.sync.aligned.m16n8k16.row.col.f32.bf16.bf16.f32 "
        "{%0,%1,%2,%3}, {%4,%5,%6,%7}, {%8,%9}, {%0,%1,%2,%3};"
        : "+f"(c[0]), "+f"(c[1]), "+f"(c[2]), "+f"(c[3])
        : "r"(a0), "r"(a1), "r"(a2), "r"(a3), "r"(b0), "r"(b1));
}
__device__ __forceinline__ void cp16(unsigned dst_smem, const void* src)
{
    asm volatile("cp.async.cg.shared.global [%0], [%1], 16;"
                 :: "r"(dst_smem), "l"(src));
}
__device__ __forceinline__ void cp_commit()
{
    asm volatile("cp.async.commit_group;");
}

// =====================================================================
// Kernel 1: coarse sim = Qbf16 @ Membf16^T via tensor cores,
// fused per-split top-10 CANDIDATE generation (rescored exactly later).
// 64 q (resident in smem) x 128 m tile, K streamed in k64 chunks via
// cp.async (3-stage ring, prefetch distance 2, 1 sync per chunk).
// 8 warps (2x4), warp tile 32x32.  grid = (SPLITS, BATCH/64)
// =====================================================================
__global__ __launch_bounds__(256) void sim_topk_mma(void)
{
    extern __shared__ __align__(16) char dsm[];
    __shared__ float Ls[64][TOPK];
    __shared__ int   Li[64][TOPK];

    const int t    = threadIdx.x;
    const int lane = t & 31;
    const int warp = t >> 5;
    const int wq   = warp >> 2;   // 0..1 : q strip
    const int wm_  = warp & 3;    // 0..3 : m strip
    const int qbase  = blockIdx.y * 64;
    const int mstart = blockIdx.x * SPLIT_SZ;
    const int mend   = min(mstart + SPLIT_SZ, MSIZE);

    const unsigned sbase = (unsigned)__cvta_generic_to_shared(dsm);
    float* Cs = (float*)(dsm + CS_OFF);

    // ---- stage resident A: 64 rows x 1024 bf16 (padded stride) ----
    #pragma unroll 4
    for (int i = 0; i < 32; i++) {
        int s = t + i * 256;                 // 8192 16B segments
        int row = s >> 7, seg = s & 127;
        uint4 v = *(const uint4*)&g_q_bf[(size_t)(qbase + row) * EMB + seg * 8];
        *(uint4*)(dsm + row * SA_STRIDE_B + seg * 16) = v;
    }

    if (t < 64) {
        #pragma unroll
        for (int i = 0; i < TOPK; i++) { Ls[t][i] = -1e30f; Li[t][i] = -1; }
    }
    __syncthreads();

    // ldmatrix base addresses
    const unsigned aAddr = sbase + (unsigned)((wq*32 + (lane & 15)) * SA_STRIDE_B
                                              + ((lane >> 4) * 16));
    const int mi = lane >> 3;
    const unsigned bRow = (unsigned)((wm_*32 + ((mi >> 1) * 8) + (lane & 7)) * SB_STRIDE_B
                                     + (mi & 1) * 16);
    const unsigned bBufBase = sbase + SA_BYTES;

    // async B chunk loader: 128 rows x 64 k bf16 (= 1024 16B segs, 4/thread)
    auto load_chunk = [&](int buf, int mb, int kb) {
        unsigned bb = bBufBase + (unsigned)buf * SB_BYTES;
        #pragma unroll
        for (int i = 0; i < 4; i++) {
            int s = t + i * 256;
            int row = s >> 3, seg = s & 7;
            int rg = mb + row; if (rg > MSIZE - 1) rg = MSIZE - 1;
            cp16(bb + (unsigned)(row * SB_STRIDE_B + seg * 16),
                 &g_mem_bf[(size_t)rg * EMB + kb + seg * 8]);
        }
        cp_commit();
    };

    for (int mb = mstart; mb < mend; mb += 128) {
        float c[2][4][4];
        #pragma unroll
        for (int a = 0; a < 2; a++)
            #pragma unroll
            for (int b = 0; b < 4; b++)
                #pragma unroll
                for (int i = 0; i < 4; i++) c[a][b][i] = 0.f;

        load_chunk(0, mb, 0);
        load_chunk(1, mb, 64);

        #pragma unroll 1
        for (int ch = 0; ch < 16; ch++) {
            // chunk ch is complete once at most the newest group is pending
            if (ch == 15) asm volatile("cp.async.wait_group 0;");
            else          asm volatile("cp.async.wait_group 1;");
            __syncthreads();
            if (ch + 2 < 16) load_chunk((ch + 2) % 3, mb, (ch + 2) * 64);

            const unsigned bA = bBufBase + (unsigned)((ch % 3)) * SB_BYTES + bRow;
            const unsigned aC = aAddr + (unsigned)ch * 128;
            #pragma unroll
            for (int kk = 0; kk < 4; kk++) {
                unsigned a[2][4];
                #pragma unroll
                for (int aq = 0; aq < 2; aq++)
                    ldsm4(a[aq][0], a[aq][1], a[aq][2], a[aq][3],
                          aC + aq * (16 * SA_STRIDE_B) + kk * 32);
                unsigned b[4][2];
                {
                    unsigned r0, r1, r2, r3;
                    ldsm4(r0, r1, r2, r3, bA + kk * 32);
                    b[0][0] = r0; b[0][1] = r1; b[1][0] = r2; b[1][1] = r3;
                    ldsm4(r0, r1, r2, r3, bA + 16 * SB_STRIDE_B + kk * 32);
                    b[2][0] = r0; b[2][1] = r1; b[3][0] = r2; b[3][1] = r3;
                }
                #pragma unroll
                for (int aq = 0; aq < 2; aq++)
                    #pragma unroll
                    for (int bn = 0; bn < 4; bn++)
                        mma_bf16(c[aq][bn], a[aq][0], a[aq][1], a[aq][2], a[aq][3],
                                 b[bn][0], b[bn][1]);
            }
        }

        // stage scores, then top-k scan
        #pragma unroll
        for (int aq = 0; aq < 2; aq++)
            #pragma unroll
            for (int bn = 0; bn < 4; bn++) {
                int r0 = wq*32 + aq*16 + (lane >> 2);
                int c0 = wm_*32 + bn*8 + (lane & 3) * 2;
                Cs[r0 * CS_STRIDE + c0]           = c[aq][bn][0];
                Cs[r0 * CS_STRIDE + c0 + 1]       = c[aq][bn][1];
                Cs[(r0+8) * CS_STRIDE + c0]       = c[aq][bn][2];
                Cs[(r0+8) * CS_STRIDE + c0 + 1]   = c[aq][bn][3];
            }
        __syncthreads();

        if (t < 64) {
            int nv = min(128, mend - mb);
            for (int j = 0; j < nv; j++) {
                float s = Cs[t * CS_STRIDE + j];
                if (s > Ls[t][TOPK - 1]) {
                    int p = TOPK - 1;
                    while (p > 0 && Ls[t][p - 1] < s) {
                        Ls[t][p] = Ls[t][p - 1];
                        Li[t][p] = Li[t][p - 1];
                        p--;
                    }
                    Ls[t][p] = s;
                    Li[t][p] = mb + j;
                }
            }
        }
        __syncthreads();
    }

    if (t < 64) {
        int q = qbase + t;
        #pragma unroll
        for (int i = 0; i < TOPK; i++)
            g_cand_i[(size_t)q * CAND + blockIdx.x * TOPK + i] = Li[t][i];
    }
}

// =====================================================================
// Kernel 2: EXACT fp32 rescore of the 160 candidates per query.
// =====================================================================
__global__ void rescore_kernel(const float* __restrict__ query,
                               const float* __restrict__ memory)
{
    __shared__ float qs[EMB];
    const int b    = blockIdx.x;
    const int t    = threadIdx.x;
    const int lane = t & 31;
    const int warp = t >> 5;

    for (int i = t; i < EMB / 4; i += 256)
        *(float4*)&qs[i * 4] = *(const float4*)&query[(size_t)b * EMB + i * 4];
    __syncthreads();

    for (int ci = warp; ci < CAND; ci += 8) {
        int midx = g_cand_i[(size_t)b * CAND + ci];
        const float* m = memory + (size_t)midx * EMB;
        float p = 0.f;
        #pragma unroll
        for (int i = 0; i < EMB / 128; i++) {
            float4 mv = *(const float4*)&m[(lane + i * 32) * 4];
            float4 qv = *(const float4*)&qs[(lane + i * 32) * 4];
            p = fmaf(qv.x, mv.x, p);
            p = fmaf(qv.y, mv.y, p);
            p = fmaf(qv.z, mv.z, p);
            p = fmaf(qv.w, mv.w, p);
        }
        #pragma unroll
        for (int off = 16; off > 0; off >>= 1)
            p += __shfl_xor_sync(0xffffffffu, p, off);
        if (lane == 0) g_cand_s[(size_t)b * CAND + ci] = p;
    }
}

// =====================================================================
// Kernel 3: exact top-10 of the 160 exact scores (1 warp/query)
// =====================================================================
__global__ void merge_topk_kernel()
{
    int gw   = (blockIdx.x * blockDim.x + threadIdx.x) >> 5;
    int lane = threadIdx.x & 31;
    if (gw >= BATCH) return;

    float s[5]; int id[5];
    #pragma unroll
    for (int l = 0; l < 5; l++) {
        int ci = lane + l * 32;
        s[l]  = g_cand_s[(size_t)gw * CAND + ci];
        id[l] = g_cand_i[(size_t)gw * CAND + ci];
    }

    for (int sel = 0; sel < TOPK; sel++) {
        float bs = -1e30f; int bi = 0x7fffffff;
        #pragma unroll
        for (int l = 0; l < 5; l++)
            if (s[l] > bs || (s[l] == bs && id[l] < bi)) { bs = s[l]; bi = id[l]; }
        #pragma unroll
        for (int off = 16; off > 0; off >>= 1) {
            float os = __shfl_down_sync(0xffffffffu, bs, off);
            int   oi = __shfl_down_sync(0xffffffffu, bi, off);
            if (os > bs || (os == bs && oi < bi)) { bs = os; bi = oi; }
        }
        bi = __shfl_sync(0xffffffffu, bi, 0);
        if (lane == 0) g_topk[gw * TOPK + sel] = bi;
        #pragma unroll
        for (int l = 0; l < 5; l++)
            if (id[l] == bi) s[l] = -1e30f;
    }
}

// =====================================================================
// Kernel 4: fp32 NT GEMM  C = A @ B^T + bias, 128x128 tile, 8x8 micro
// grid = (N/128, M/128, nheads)
// =====================================================================
__global__ __launch_bounds__(256) void gemm_nt128(
    const float* __restrict__ A, int lda, long hsA,
    const float* __restrict__ B, long hsB,
    const float* __restrict__ bias, int hsBias,
    float* __restrict__ C, int ldc, long hsC, int K)
{
    __shared__ float As[16][132];
    __shared__ float Bs[16][132];

    const float* Az = A + (size_t)blockIdx.z * hsA;
    const float* Bz = B + (size_t)blockIdx.z * hsB;
    const float* bz = bias + (size_t)blockIdx.z * hsBias;
    float*       Cz = C + (size_t)blockIdx.z * hsC;

    const int t  = threadIdx.x;
    const int tx = t & 15;
    const int ty = t >> 4;
    const int rbase = blockIdx.y * 128;
    const int cbase = blockIdx.x * 128;

    float acc[8][8];
    #pragma unroll
    for (int i = 0; i < 8; i++)
        #pragma unroll
        for (int j = 0; j < 8; j++) acc[i][j] = 0.f;

    for (int kb = 0; kb < K; kb += 16) {
        #pragma unroll
        for (int l = 0; l < 8; l++) {
            int lin = t + l * 256;
            int kk  = lin & 15;
            int row = lin >> 4;
            As[kk][row] = Az[(size_t)(rbase + row) * lda + kb + kk];
            Bs[kk][row] = Bz[(size_t)(cbase + row) * EMB + kb + kk];
        }
        __syncthreads();
        #pragma unroll
        for (int kk = 0; kk < 16; kk++) {
            float a[8], b[8];
            *(float4*)&a[0] = *(const float4*)&As[kk][ty * 8];
            *(float4*)&a[4] = *(const float4*)&As[kk][ty * 8 + 4];
            *(float4*)&b[0] = *(const float4*)&Bs[kk][tx * 8];
            *(float4*)&b[4] = *(const float4*)&Bs[kk][tx * 8 + 4];
            #pragma unroll
            for (int i = 0; i < 8; i++)
                #pragma unroll
                for (int j = 0; j < 8; j++)
                    acc[i][j] = fmaf(a[i], b[j], acc[i][j]);
        }
        __syncthreads();
    }

    #pragma unroll
    for (int i = 0; i < 8; i++)
        #pragma unroll
        for (int j = 0; j < 8; j++)
            Cz[(size_t)(rbase + ty * 8 + i) * ldc + cbase + tx * 8 + j] =
                acc[i][j] + bz[cbase + tx * 8 + j];
}

// =====================================================================
// Kernel 5: T[b,h,:] = qp_h[b,:] @ w_k_h  (NN, K=128), 128x128 tile, 8x8
// grid = (EMB/128, BATCH/128, HEADS)
// =====================================================================
__global__ __launch_bounds__(256) void gemm_nn128_T(
    const float* __restrict__ qp,
    const float* __restrict__ wk,
    float* __restrict__ T)
{
    __shared__ float As[16][132];
    __shared__ float Bs[16][132];

    const int h  = blockIdx.z;
    const int t  = threadIdx.x;
    const int tx = t & 15;
    const int ty = t >> 4;
    const int rbase = blockIdx.y * 128;
    const int cbase = blockIdx.x * 128;
    const float* Bz = wk + (size_t)h * HDIM * EMB;

    float acc[8][8];
    #pragma unroll
    for (int i = 0; i < 8; i++)
        #pragma unroll
        for (int j = 0; j < 8; j++) acc[i][j] = 0.f;

    for (int kb = 0; kb < HDIM; kb += 16) {
        #pragma unroll
        for (int l = 0; l < 8; l++) {
            int lin = t + l * 256;
            {   // A: qp head slice, k-major staging
                int kk  = lin & 15;
                int row = lin >> 4;
                As[kk][row] = qp[(size_t)(rbase + row) * EMB + h * HDIM + kb + kk];
            }
            {   // B: w_k_h rows are k (coalesced over output col)
                int col = lin & 127;
                int kk  = lin >> 7;
                Bs[kk][col] = Bz[(size_t)(kb + kk) * EMB + cbase + col];
            }
        }
        __syncthreads();
        #pragma unroll
        for (int kk = 0; kk < 16; kk++) {
            float a[8], b[8];
            *(float4*)&a[0] = *(const float4*)&As[kk][ty * 8];
            *(float4*)&a[4] = *(const float4*)&As[kk][ty * 8 + 4];
            *(float4*)&b[0] = *(const float4*)&Bs[kk][tx * 8];
            *(float4*)&b[4] = *(const float4*)&Bs[kk][tx * 8 + 4];
            #pragma unroll
            for (int i = 0; i < 8; i++)
                #pragma unroll
                for (int j = 0; j < 8; j++)
                    acc[i][j] = fmaf(a[i], b[j], acc[i][j]);
        }
        __syncthreads();
    }

    #pragma unroll
    for (int i = 0; i < 8; i++)
        #pragma unroll
        for (int j = 0; j < 8; j++)
            T[(size_t)(rbase + ty * 8 + i) * (HEADS * EMB) + h * EMB +
              cbase + tx * 8 + j] = acc[i][j];
}

// =====================================================================
// Kernel 6: attention. 1 CTA per batch row, 8 warps = 8 heads.
// =====================================================================
__global__ void attention2(const float* __restrict__ mem,
                           const float* __restrict__ b_k)
{
    __shared__ float Ms[TOPK][EMB];   // 40 KB
    __shared__ int   idxs[TOPK];

    const int b = blockIdx.x;
    const int t = threadIdx.x;
    const int lane = t & 31;
    const int h = t >> 5;

    if (t < TOPK) idxs[t] = g_topk[b * TOPK + t];
    __syncthreads();

    for (int i = t; i < TOPK * (EMB / 4); i += 256) {
        int k  = i >> 8;
        int e4 = i & 255;
        *(float4*)&Ms[k][e4 * 4] =
            *(const float4*)&mem[(size_t)idxs[k] * EMB + e4 * 4];
    }
    __syncthreads();

    float Tr[32];
    const float* Tp = g_T + (size_t)b * HEADS * EMB + h * EMB;
    #pragma unroll
    for (int i = 0; i < 32; i++) Tr[i] = Tp[lane + i * 32];

    float cb = 0.f;
    const float* qpp = g_qp + (size_t)b * EMB + h * HDIM;
    const float* bkp = b_k + h * HDIM;
    #pragma unroll
    for (int j = 0; j < 4; j++) cb = fmaf(qpp[lane*4+j], bkp[lane*4+j], cb);
    #pragma unroll
    for (int off = 16; off > 0; off >>= 1)
        cb += __shfl_xor_sync(0xffffffffu, cb, off);

    const float scale = 0.08838834764831845f;  // 1/sqrt(128)
    float sc[TOPK];
    #pragma unroll
    for (int k = 0; k < TOPK; k++) {
        float p = 0.f;
        #pragma unroll
        for (int i = 0; i < 32; i++) p = fmaf(Tr[i], Ms[k][lane + i * 32], p);
        #pragma unroll
        for (int off = 16; off > 0; off >>= 1)
            p += __shfl_xor_sync(0xffffffffu, p, off);
        sc[k] = (p + cb) * scale;
    }

    float mx = sc[0];
    #pragma unroll
    for (int k = 1; k < TOPK; k++) mx = fmaxf(mx, sc[k]);
    float w[TOPK], sum = 0.f;
    #pragma unroll
    for (int k = 0; k < TOPK; k++) { w[k] = expf(sc[k] - mx); sum += w[k]; }
    float inv = 1.f / sum;
    #pragma unroll
    for (int k = 0; k < TOPK; k++) w[k] *= inv;

    float* wmp = g_wm + (size_t)b * HEADS * EMB + h * EMB;
    #pragma unroll
    for (int i = 0; i < 32; i++) {
        int e = lane + i * 32;
        float a = 0.f;
        #pragma unroll
        for (int k = 0; k < TOPK; k++) a = fmaf(w[k], Ms[k][e], a);
        wmp[e] = a;
    }
}

// =====================================================================
extern "C" void kernel_launch(void* const* d_in, const int* in_sizes, int n_in,
                              void* d_out, int out_size)
{
    const float* query  = (const float*)d_in[0];
    const float* memory = (const float*)d_in[1];
    const float* w_q    = (const float*)d_in[2];
    const float* w_k    = (const float*)d_in[3];
    const float* w_v    = (const float*)d_in[4];
    const float* b_q    = (const float*)d_in[5];
    const float* b_k    = (const float*)d_in[6];
    const float* b_v    = (const float*)d_in[7];
    const float* w_o    = (const float*)d_in[8];
    const float* b_o    = (const float*)d_in[9];
    float* out = (float*)d_out;

    __nv_bfloat16 *mbf, *qbf;
    float *qp, *T, *wm, *ctx;
    cudaGetSymbolAddress((void**)&mbf, g_mem_bf);
    cudaGetSymbolAddress((void**)&qbf, g_q_bf);
    cudaGetSymbolAddress((void**)&qp,  g_qp);
    cudaGetSymbolAddress((void**)&T,   g_T);
    cudaGetSymbolAddress((void**)&wm,  g_wm);
    cudaGetSymbolAddress((void**)&ctx, g_ctx);

    // opt-in smem for the resident-A sim kernel (idempotent)
    cudaFuncSetAttribute(sim_topk_mma,
                         cudaFuncAttributeMaxDynamicSharedMemorySize, SIM_DSMEM);

    // 1) bf16 conversions (candidate-generation path only)
    to_bf16_kernel<<<(MSIZE*EMB/4 + 255)/256, 256>>>(memory, mbf, MSIZE*EMB/4);
    to_bf16_kernel<<<(BATCH*EMB/4 + 255)/256, 256>>>(query,  qbf, BATCH*EMB/4);

    // 2) tensor-core coarse similarity -> 160 candidates/query
    sim_topk_mma<<<dim3(SPLITS, BATCH/64), 256, SIM_DSMEM>>>();

    // 3) exact fp32 rescore of candidates
    rescore_kernel<<<BATCH, 256>>>(query, memory);

    // 4) exact top-10
    merge_topk_kernel<<<BATCH/8, 256>>>();

    // 5) q projection: qp = query @ w_q^T + b_q
    gemm_nt128<<<dim3(8, 16, 1), 256>>>(query, EMB, 0, w_q, 0, b_q, 0,
                                        qp, EMB, 0, EMB);

    // 6) T[b,h,:] = qp_h @ w_k_h   (absorbs k-projection)
    gemm_nn128_T<<<dim3(8, 16, 8), 256>>>(qp, w_k, T);

    // 7) attention: scores, softmax, weighted memory sum
    attention2<<<BATCH, 256>>>(memory, b_k);

    // 8) ctx_h = wm_h @ w_v_h^T + b_v_h   (absorbs v-projection)
    gemm_nt128<<<dim3(1, 16, 8), 256>>>(wm, HEADS*EMB, EMB,
                                        w_v, (long)HDIM*EMB,
                                        b_v, HDIM,
                                        ctx, EMB, HDIM, EMB);

    // 9) out = ctx @ w_o^T + b_o
    gemm_nt128<<<dim3(8, 16, 1), 256>>>(ctx, EMB, 0, w_o, 0, b_o, 0,
                                        out, EMB, 0, EMB);
}

// round 6
// speedup vs baseline: 10.3710x; 1.5921x over previous
#include <cuda_runtime.h>
#include <cuda.h>
#include <cuda_bf16.h>
#include <math.h>
#include <stdint.h>

#define BATCH   2048
#define EMB     1024
#define MSIZE   100000
#define HEADS   8
#define HDIM    128
#define TOPK    10
#define SPLITS  16
#define SPLIT_SZ 6272           // 49 m-blocks of 128; 16*6272=100352 >= 100000
#define CAND    (SPLITS*TOPK)   // 160 candidates per query

// ---- sim kernel geometry (TMA + mma.sync) ----
#define QTILE   128
#define MTILE   128
#define KCH     64                       // 64 bf16 = 128 B = SW128 atom row
#define NKC     (EMB/KCH)                // 16 chunks per m-block
#define NMB     (SPLIT_SZ/MTILE)         // 49 m-blocks per split
#define NCHUNK  (NMB*NKC)                // 784
#define NSTAGE  4
#define A_BYTES (QTILE*128)              // 16384 (128 rows x 128B)
#define B_BYTES (MTILE*128)              // 16384
#define STAGE_BYTES (A_BYTES+B_BYTES)    // 32768
#define CS_OFF  (NSTAGE*STAGE_BYTES)     // 131072
#define CS_STRIDE 132
#define SIM_DSMEM (CS_OFF + QTILE*CS_STRIDE*4)   // 198656

// ---------------- device scratch ----------------
__device__ __nv_bfloat16 g_mem_bf[MSIZE*EMB];   // 200 MB
__device__ __nv_bfloat16 g_q_bf  [BATCH*EMB];   // 4 MB
__device__ float g_qp [BATCH*EMB];
__device__ float g_T  [BATCH*HEADS*EMB];
__device__ float g_wm [BATCH*HEADS*EMB];
__device__ float g_ctx[BATCH*EMB];
__device__ float g_cand_s[BATCH*CAND];
__device__ int   g_cand_i[BATCH*CAND];
__device__ int   g_topk [BATCH*TOPK];

// =====================================================================
// PTX helpers (sm_90-era only: TMA, mbarrier, ldmatrix, mma.sync)
// =====================================================================
__device__ __forceinline__ unsigned sm2u32(const void* p) {
    unsigned a;
    asm("{ .reg .u64 t; cvta.to.shared.u64 t, %1; cvt.u32.u64 %0, t; }"
        : "=r"(a) : "l"(p));
    return a;
}
#define MBAR_INIT(a, n) \
    asm volatile("mbarrier.init.shared.b64 [%0], %1;" :: "r"(a), "r"(n) : "memory")
#define MBAR_EXPECT_TX(a, n) \
    asm volatile("mbarrier.arrive.expect_tx.shared.b64 _, [%0], %1;" :: "r"(a), "r"(n) : "memory")
#define MBAR_ARRIVE(a) \
    asm volatile("mbarrier.arrive.shared.b64 _, [%0];" :: "r"(a) : "memory")
#define MBAR_WAIT(a, ph) do {                                             \
    asm volatile(                                                         \
        "{\n\t.reg .pred P1;\n\t"                                         \
        "W%=:\n\t"                                                        \
        "mbarrier.try_wait.parity.acquire.cta.shared::cta.b64 P1, [%0], %1, 0x989680;\n\t" \
        "@P1 bra.uni D%=;\n\t"                                            \
        "bra.uni W%=;\n\t"                                                \
        "D%=:\n\t}"                                                       \
        :: "r"(a), "r"(ph) : "memory");                                   \
} while (0)

#define TMA2D(dst, map, cx, cy, mbar) \
    asm volatile( \
        "cp.async.bulk.tensor.2d.shared::cta.global.tile.mbarrier::complete_tx::bytes " \
        "[%0], [%1, {%2, %3}], [%4];" \
        :: "r"(dst), "l"(map), "r"(cx), "r"(cy), "r"(mbar) : "memory")

__device__ __forceinline__ void ldsm4(unsigned &r0, unsigned &r1,
                                      unsigned &r2, unsigned &r3, unsigned addr)
{
    asm volatile("ldmatrix.sync.aligned.m8n8.x4.shared.b16 {%0,%1,%2,%3}, [%4];"
                 : "=r"(r0), "=r"(r1), "=r"(r2), "=r"(r3) : "r"(addr));
}
__device__ __forceinline__ void mma_bf16(float* c,
    unsigned a0, unsigned a1, unsigned a2, unsigned a3,
    unsigned b0, unsigned b1)
{
    asm volatile(
        "mma.sync.aligned.m16n8k16.row.col.f32.bf16.bf16.f32 "
        "{%0,%1,%2,%3}, {%4,%5,%6,%7}, {%8,%9}, {%0,%1,%2,%3};"
        : "+f"(c[0]), "+f"(c[1]), "+f"(c[2]), "+f"(c[3])
        : "r"(a0), "r"(a1), "r"(a2), "r"(a3), "r"(b0), "r"(b1));
}

// =====================================================================
// fp32 -> bf16 conversion (vectorized x4)
// =====================================================================
__global__ void to_bf16_kernel(const float* __restrict__ src,
                               __nv_bfloat16* __restrict__ dst, int n4)
{
    int i = blockIdx.x * blockDim.x + threadIdx.x;
    if (i >= n4) return;
    float4 v = ((const float4*)src)[i];
    __nv_bfloat16 o[4];
    o[0] = __float2bfloat16(v.x); o[1] = __float2bfloat16(v.y);
    o[2] = __float2bfloat16(v.z); o[3] = __float2bfloat16(v.w);
    ((uint2*)dst)[i] = *(uint2*)o;
}

// =====================================================================
// Kernel 1: coarse sim = Qbf16 @ Membf16^T, TMA(SW128)-fed mma.sync,
// fused per-split top-10 candidate generation.
// CTA: 128q x 128m, 8 warps (2x4), warp tile 64x32, k64 chunks, 4-stage ring.
// grid = (BATCH/128, SPLITS), block = 256.
// =====================================================================
__global__ __launch_bounds__(256, 1) void sim_topk_tma(
    const __grid_constant__ CUtensorMap tmQ,
    const __grid_constant__ CUtensorMap tmM)
{
    extern __shared__ __align__(1024) char dsm[];
    __shared__ __align__(8) unsigned long long mbar[8];  // [0..3] full, [4..7] empty
    __shared__ float Ls[QTILE][TOPK];
    __shared__ int   Li[QTILE][TOPK];

    const int t    = threadIdx.x;
    const int lane = t & 31;
    const int warp = t >> 5;
    const int wq   = warp >> 2;        // 0..1  (64 q rows each)
    const int wm   = warp & 3;         // 0..3  (32 m cols each)
    const int qbase  = blockIdx.x * QTILE;
    const int mstart = blockIdx.y * SPLIT_SZ;

    const unsigned sb  = sm2u32(dsm);
    const unsigned mb0 = sm2u32(&mbar[0]);
    float* Cs = (float*)(dsm + CS_OFF);

    if (t == 0) {
        #pragma unroll
        for (int i = 0; i < 4; i++) MBAR_INIT(mb0 + i * 8, 1);       // full
        #pragma unroll
        for (int i = 4; i < 8; i++) MBAR_INIT(mb0 + i * 8, 256);     // empty
    }
    if (t < QTILE) {
        #pragma unroll
        for (int i = 0; i < TOPK; i++) { Ls[t][i] = -1e30f; Li[t][i] = 0; }
    }
    __syncthreads();

    // prologue: fill all 4 stages
    if (t == 0) {
        #pragma unroll
        for (int g = 0; g < 4; g++) {
            unsigned fb = mb0 + g * 8;
            MBAR_EXPECT_TX(fb, STAGE_BYTES);
            TMA2D(sb + g * STAGE_BYTES,           &tmQ, (g & 15) * KCH, qbase, fb);
            TMA2D(sb + g * STAGE_BYTES + A_BYTES, &tmM, (g & 15) * KCH,
                  mstart + (g >> 4) * MTILE, fb);
        }
    }

    // per-lane swizzled ldmatrix address components (SW128: c' = c ^ (row&7))
    const int xm  = lane & 7;
    const int ahi = lane >> 4;          // A 16B-col selector
    const int mi  = lane >> 3;          // B matrix index 0..3
    const int blo = mi & 1;             // B 16B-col selector
    unsigned aRow[4], bRow[2];
    #pragma unroll
    for (int t4 = 0; t4 < 4; t4++)
        aRow[t4] = (unsigned)((wq * 64 + t4 * 16 + (lane & 15)) * 128);
    #pragma unroll
    for (int p = 0; p < 2; p++)
        bRow[p] = (unsigned)((wm * 32 + p * 16 + ((mi >> 1) * 8) + (lane & 7)) * 128)
                  + (unsigned)A_BYTES;

    for (int mbi = 0; mbi < NMB; mbi++) {
        float c[4][4][4];
        #pragma unroll
        for (int i = 0; i < 4; i++)
            #pragma unroll
            for (int j = 0; j < 4; j++)
                #pragma unroll
                for (int k = 0; k < 4; k++) c[i][j][k] = 0.f;

        for (int kc = 0; kc < NKC; kc++) {
            const int g = mbi * NKC + kc;
            const int s = g & 3;
            const unsigned stg = sb + (unsigned)s * STAGE_BYTES;

            MBAR_WAIT(mb0 + s * 8, (g >> 2) & 1);

            #pragma unroll
            for (int kk = 0; kk < 4; kk++) {
                // B frags: 2 ldsm.x4 -> 4 n8 frags
                unsigned b[4][2];
                {
                    const unsigned cB = (unsigned)((((kk << 1) | blo) ^ xm) << 4);
                    unsigned r0, r1, r2, r3;
                    ldsm4(r0, r1, r2, r3, stg + bRow[0] + cB);
                    b[0][0] = r0; b[0][1] = r1; b[1][0] = r2; b[1][1] = r3;
                    ldsm4(r0, r1, r2, r3, stg + bRow[1] + cB);
                    b[2][0] = r0; b[2][1] = r1; b[3][0] = r2; b[3][1] = r3;
                }
                const unsigned cA = (unsigned)((((kk << 1) | ahi) ^ xm) << 4);
                #pragma unroll
                for (int t4 = 0; t4 < 4; t4++) {
                    unsigned a0, a1, a2, a3;
                    ldsm4(a0, a1, a2, a3, stg + aRow[t4] + cA);
                    #pragma unroll
                    for (int bn = 0; bn < 4; bn++)
                        mma_bf16(c[t4][bn], a0, a1, a2, a3, b[bn][0], b[bn][1]);
                }
            }

            MBAR_ARRIVE(mb0 + 32 + s * 8);     // stage consumed (count 256)

            // producer: refill this stage for chunk g+4
            if (t == 0) {
                const int g2 = g + 4;
                if (g2 < NCHUNK) {
                    MBAR_WAIT(mb0 + 32 + s * 8, (g >> 2) & 1);
                    unsigned fb = mb0 + s * 8;
                    MBAR_EXPECT_TX(fb, STAGE_BYTES);
                    const int kc2 = g2 & 15, mb2 = g2 >> 4;
                    TMA2D(sb + s * STAGE_BYTES,           &tmQ, kc2 * KCH, qbase, fb);
                    TMA2D(sb + s * STAGE_BYTES + A_BYTES, &tmM, kc2 * KCH,
                          mstart + mb2 * MTILE, fb);
                }
            }
        }

        // ---- epilogue: stage scores, scan exact per-split top-10 ----
        #pragma unroll
        for (int t4 = 0; t4 < 4; t4++)
            #pragma unroll
            for (int bn = 0; bn < 4; bn++) {
                int r0 = wq * 64 + t4 * 16 + (lane >> 2);
                int c0 = wm * 32 + bn * 8 + (lane & 3) * 2;
                Cs[r0 * CS_STRIDE + c0]         = c[t4][bn][0];
                Cs[r0 * CS_STRIDE + c0 + 1]     = c[t4][bn][1];
                Cs[(r0 + 8) * CS_STRIDE + c0]     = c[t4][bn][2];
                Cs[(r0 + 8) * CS_STRIDE + c0 + 1] = c[t4][bn][3];
            }
        __syncthreads();

        const int mb_base = mstart + mbi * MTILE;
        if (t < QTILE) {
            int nv = MSIZE - mb_base;
            if (nv > MTILE) nv = MTILE;
            for (int j = 0; j < nv; j++) {
                float s = Cs[t * CS_STRIDE + j];
                if (s > Ls[t][TOPK - 1]) {
                    int p = TOPK - 1;
                    while (p > 0 && Ls[t][p - 1] < s) {
                        Ls[t][p] = Ls[t][p - 1];
                        Li[t][p] = Li[t][p - 1];
                        p--;
                    }
                    Ls[t][p] = s;
                    Li[t][p] = mb_base + j;
                }
            }
        }
        __syncthreads();
    }

    if (t < QTILE) {
        int q = qbase + t;
        #pragma unroll
        for (int i = 0; i < TOPK; i++)
            g_cand_i[(size_t)q * CAND + blockIdx.y * TOPK + i] = Li[t][i];
    }
}

// =====================================================================
// Kernel 2: EXACT fp32 rescore of the 160 candidates per query.
// =====================================================================
__global__ void rescore_kernel(const float* __restrict__ query,
                               const float* __restrict__ memory)
{
    __shared__ float qs[EMB];
    const int b    = blockIdx.x;
    const int t    = threadIdx.x;
    const int lane = t & 31;
    const int warp = t >> 5;

    for (int i = t; i < EMB / 4; i += 256)
        *(float4*)&qs[i * 4] = *(const float4*)&query[(size_t)b * EMB + i * 4];
    __syncthreads();

    for (int ci = warp; ci < CAND; ci += 8) {
        int midx = g_cand_i[(size_t)b * CAND + ci];
        const float* m = memory + (size_t)midx * EMB;
        float p = 0.f;
        #pragma unroll
        for (int i = 0; i < EMB / 128; i++) {
            float4 mv = *(const float4*)&m[(lane + i * 32) * 4];
            float4 qv = *(const float4*)&qs[(lane + i * 32) * 4];
            p = fmaf(qv.x, mv.x, p);
            p = fmaf(qv.y, mv.y, p);
            p = fmaf(qv.z, mv.z, p);
            p = fmaf(qv.w, mv.w, p);
        }
        #pragma unroll
        for (int off = 16; off > 0; off >>= 1)
            p += __shfl_xor_sync(0xffffffffu, p, off);
        if (lane == 0) g_cand_s[(size_t)b * CAND + ci] = p;
    }
}

// =====================================================================
// Kernel 3: exact top-10 of the 160 exact scores (1 warp/query)
// =====================================================================
__global__ void merge_topk_kernel()
{
    int gw   = (blockIdx.x * blockDim.x + threadIdx.x) >> 5;
    int lane = threadIdx.x & 31;
    if (gw >= BATCH) return;

    float s[5]; int id[5];
    #pragma unroll
    for (int l = 0; l < 5; l++) {
        int ci = lane + l * 32;
        s[l]  = g_cand_s[(size_t)gw * CAND + ci];
        id[l] = g_cand_i[(size_t)gw * CAND + ci];
    }

    for (int sel = 0; sel < TOPK; sel++) {
        float bs = -1e30f; int bi = 0x7fffffff;
        #pragma unroll
        for (int l = 0; l < 5; l++)
            if (s[l] > bs || (s[l] == bs && id[l] < bi)) { bs = s[l]; bi = id[l]; }
        #pragma unroll
        for (int off = 16; off > 0; off >>= 1) {
            float os = __shfl_down_sync(0xffffffffu, bs, off);
            int   oi = __shfl_down_sync(0xffffffffu, bi, off);
            if (os > bs || (os == bs && oi < bi)) { bs = os; bi = oi; }
        }
        bi = __shfl_sync(0xffffffffu, bi, 0);
        if (lane == 0) g_topk[gw * TOPK + sel] = bi;
        #pragma unroll
        for (int l = 0; l < 5; l++)
            if (id[l] == bi) s[l] = -1e30f;
    }
}

// =====================================================================
// Kernel 4: fp32 NT GEMM  C = A @ B^T + bias, 128x128 tile, 8x8 micro
// =====================================================================
__global__ __launch_bounds__(256) void gemm_nt128(
    const float* __restrict__ A, int lda, long hsA,
    const float* __restrict__ B, long hsB,
    const float* __restrict__ bias, int hsBias,
    float* __restrict__ C, int ldc, long hsC, int K)
{
    __shared__ float As[16][132];
    __shared__ float Bs[16][132];

    const float* Az = A + (size_t)blockIdx.z * hsA;
    const float* Bz = B + (size_t)blockIdx.z * hsB;
    const float* bz = bias + (size_t)blockIdx.z * hsBias;
    float*       Cz = C + (size_t)blockIdx.z * hsC;

    const int t  = threadIdx.x;
    const int tx = t & 15;
    const int ty = t >> 4;
    const int rbase = blockIdx.y * 128;
    const int cbase = blockIdx.x * 128;

    float acc[8][8];
    #pragma unroll
    for (int i = 0; i < 8; i++)
        #pragma unroll
        for (int j = 0; j < 8; j++) acc[i][j] = 0.f;

    for (int kb = 0; kb < K; kb += 16) {
        #pragma unroll
        for (int l = 0; l < 8; l++) {
            int lin = t + l * 256;
            int kk  = lin & 15;
            int row = lin >> 4;
            As[kk][row] = Az[(size_t)(rbase + row) * lda + kb + kk];
            Bs[kk][row] = Bz[(size_t)(cbase + row) * EMB + kb + kk];
        }
        __syncthreads();
        #pragma unroll
        for (int kk = 0; kk < 16; kk++) {
            float a[8], b[8];
            *(float4*)&a[0] = *(const float4*)&As[kk][ty * 8];
            *(float4*)&a[4] = *(const float4*)&As[kk][ty * 8 + 4];
            *(float4*)&b[0] = *(const float4*)&Bs[kk][tx * 8];
            *(float4*)&b[4] = *(const float4*)&Bs[kk][tx * 8 + 4];
            #pragma unroll
            for (int i = 0; i < 8; i++)
                #pragma unroll
                for (int j = 0; j < 8; j++)
                    acc[i][j] = fmaf(a[i], b[j], acc[i][j]);
        }
        __syncthreads();
    }

    #pragma unroll
    for (int i = 0; i < 8; i++)
        #pragma unroll
        for (int j = 0; j < 8; j++)
            Cz[(size_t)(rbase + ty * 8 + i) * ldc + cbase + tx * 8 + j] =
                acc[i][j] + bz[cbase + tx * 8 + j];
}

// =====================================================================
// Kernel 5: T[b,h,:] = qp_h[b,:] @ w_k_h  (NN, K=128), 128x128 tile
// =====================================================================
__global__ __launch_bounds__(256) void gemm_nn128_T(
    const float* __restrict__ qp,
    const float* __restrict__ wk,
    float* __restrict__ T)
{
    __shared__ float As[16][132];
    __shared__ float Bs[16][132];

    const int h  = blockIdx.z;
    const int t  = threadIdx.x;
    const int tx = t & 15;
    const int ty = t >> 4;
    const int rbase = blockIdx.y * 128;
    const int cbase = blockIdx.x * 128;
    const float* Bz = wk + (size_t)h * HDIM * EMB;

    float acc[8][8];
    #pragma unroll
    for (int i = 0; i < 8; i++)
        #pragma unroll
        for (int j = 0; j < 8; j++) acc[i][j] = 0.f;

    for (int kb = 0; kb < HDIM; kb += 16) {
        #pragma unroll
        for (int l = 0; l < 8; l++) {
            int lin = t + l * 256;
            {
                int kk  = lin & 15;
                int row = lin >> 4;
                As[kk][row] = qp[(size_t)(rbase + row) * EMB + h * HDIM + kb + kk];
            }
            {
                int col = lin & 127;
                int kk  = lin >> 7;
                Bs[kk][col] = Bz[(size_t)(kb + kk) * EMB + cbase + col];
            }
        }
        __syncthreads();
        #pragma unroll
        for (int kk = 0; kk < 16; kk++) {
            float a[8], b[8];
            *(float4*)&a[0] = *(const float4*)&As[kk][ty * 8];
            *(float4*)&a[4] = *(const float4*)&As[kk][ty * 8 + 4];
            *(float4*)&b[0] = *(const float4*)&Bs[kk][tx * 8];
            *(float4*)&b[4] = *(const float4*)&Bs[kk][tx * 8 + 4];
            #pragma unroll
            for (int i = 0; i < 8; i++)
                #pragma unroll
                for (int j = 0; j < 8; j++)
                    acc[i][j] = fmaf(a[i], b[j], acc[i][j]);
        }
        __syncthreads();
    }

    #pragma unroll
    for (int i = 0; i < 8; i++)
        #pragma unroll
        for (int j = 0; j < 8; j++)
            T[(size_t)(rbase + ty * 8 + i) * (HEADS * EMB) + h * EMB +
              cbase + tx * 8 + j] = acc[i][j];
}

// =====================================================================
// Kernel 6: attention. 1 CTA per batch row, 8 warps = 8 heads.
// =====================================================================
__global__ void attention2(const float* __restrict__ mem,
                           const float* __restrict__ b_k)
{
    __shared__ float Ms[TOPK][EMB];
    __shared__ int   idxs[TOPK];

    const int b = blockIdx.x;
    const int t = threadIdx.x;
    const int lane = t & 31;
    const int h = t >> 5;

    if (t < TOPK) idxs[t] = g_topk[b * TOPK + t];
    __syncthreads();

    for (int i = t; i < TOPK * (EMB / 4); i += 256) {
        int k  = i >> 8;
        int e4 = i & 255;
        *(float4*)&Ms[k][e4 * 4] =
            *(const float4*)&mem[(size_t)idxs[k] * EMB + e4 * 4];
    }
    __syncthreads();

    float Tr[32];
    const float* Tp = g_T + (size_t)b * HEADS * EMB + h * EMB;
    #pragma unroll
    for (int i = 0; i < 32; i++) Tr[i] = Tp[lane + i * 32];

    float cb = 0.f;
    const float* qpp = g_qp + (size_t)b * EMB + h * HDIM;
    const float* bkp = b_k + h * HDIM;
    #pragma unroll
    for (int j = 0; j < 4; j++) cb = fmaf(qpp[lane*4+j], bkp[lane*4+j], cb);
    #pragma unroll
    for (int off = 16; off > 0; off >>= 1)
        cb += __shfl_xor_sync(0xffffffffu, cb, off);

    const float scale = 0.08838834764831845f;  // 1/sqrt(128)
    float sc[TOPK];
    #pragma unroll
    for (int k = 0; k < TOPK; k++) {
        float p = 0.f;
        #pragma unroll
        for (int i = 0; i < 32; i++) p = fmaf(Tr[i], Ms[k][lane + i * 32], p);
        #pragma unroll
        for (int off = 16; off > 0; off >>= 1)
            p += __shfl_xor_sync(0xffffffffu, p, off);
        sc[k] = (p + cb) * scale;
    }

    float mx = sc[0];
    #pragma unroll
    for (int k = 1; k < TOPK; k++) mx = fmaxf(mx, sc[k]);
    float w[TOPK], sum = 0.f;
    #pragma unroll
    for (int k = 0; k < TOPK; k++) { w[k] = expf(sc[k] - mx); sum += w[k]; }
    float inv = 1.f / sum;
    #pragma unroll
    for (int k = 0; k < TOPK; k++) w[k] *= inv;

    float* wmp = g_wm + (size_t)b * HEADS * EMB + h * EMB;
    #pragma unroll
    for (int i = 0; i < 32; i++) {
        int e = lane + i * 32;
        float a = 0.f;
        #pragma unroll
        for (int k = 0; k < TOPK; k++) a = fmaf(w[k], Ms[k][e], a);
        wmp[e] = a;
    }
}

// =====================================================================
// host: tensormap encode via runtime-resolved driver entry point
// =====================================================================
typedef CUresult (*encode_fn_t)(
    CUtensorMap*, CUtensorMapDataType, cuuint32_t, void*,
    const cuuint64_t*, const cuuint64_t*, const cuuint32_t*, const cuuint32_t*,
    CUtensorMapInterleave, CUtensorMapSwizzle, CUtensorMapL2promotion,
    CUtensorMapFloatOOBfill);

static void encode_2d_bf16(encode_fn_t enc, CUtensorMap* tm, void* base,
                           uint64_t rows, uint32_t box_rows)
{
    cuuint64_t dims[2]    = {EMB, rows};
    cuuint64_t strides[1] = {EMB * 2};
    cuuint32_t box[2]     = {KCH, box_rows};
    cuuint32_t es[2]      = {1, 1};
    enc(tm, CU_TENSOR_MAP_DATA_TYPE_BFLOAT16, 2, base, dims, strides, box, es,
        CU_TENSOR_MAP_INTERLEAVE_NONE, CU_TENSOR_MAP_SWIZZLE_128B,
        CU_TENSOR_MAP_L2_PROMOTION_L2_128B, CU_TENSOR_MAP_FLOAT_OOB_FILL_NONE);
}

// =====================================================================
extern "C" void kernel_launch(void* const* d_in, const int* in_sizes, int n_in,
                              void* d_out, int out_size)
{
    const float* query  = (const float*)d_in[0];
    const float* memory = (const float*)d_in[1];
    const float* w_q    = (const float*)d_in[2];
    const float* w_k    = (const float*)d_in[3];
    const float* w_v    = (const float*)d_in[4];
    const float* b_q    = (const float*)d_in[5];
    const float* b_k    = (const float*)d_in[6];
    const float* b_v    = (const float*)d_in[7];
    const float* w_o    = (const float*)d_in[8];
    const float* b_o    = (const float*)d_in[9];
    float* out = (float*)d_out;

    __nv_bfloat16 *mbf, *qbf;
    float *qp, *T, *wm, *ctx;
    cudaGetSymbolAddress((void**)&mbf, g_mem_bf);
    cudaGetSymbolAddress((void**)&qbf, g_q_bf);
    cudaGetSymbolAddress((void**)&qp,  g_qp);
    cudaGetSymbolAddress((void**)&T,   g_T);
    cudaGetSymbolAddress((void**)&wm,  g_wm);
    cudaGetSymbolAddress((void**)&ctx, g_ctx);

    // tensormaps (host-side; baked into kernel params)
    encode_fn_t enc = nullptr;
    cudaDriverEntryPointQueryResult qr;
    cudaGetDriverEntryPointByVersion("cuTensorMapEncodeTiled", (void**)&enc,
                                     12000, cudaEnableDefault, &qr);
    CUtensorMap tmQ, tmM;
    encode_2d_bf16(enc, &tmQ, qbf, BATCH, QTILE);
    encode_2d_bf16(enc, &tmM, mbf, MSIZE, MTILE);

    cudaFuncSetAttribute(sim_topk_tma,
                         cudaFuncAttributeMaxDynamicSharedMemorySize, SIM_DSMEM);

    // 1) bf16 conversions (candidate-generation path only)
    to_bf16_kernel<<<(MSIZE*EMB/4 + 255)/256, 256>>>(memory, mbf, MSIZE*EMB/4);
    to_bf16_kernel<<<(BATCH*EMB/4 + 255)/256, 256>>>(query,  qbf, BATCH*EMB/4);

    // 2) TMA+mma.sync coarse similarity -> 160 candidates/query
    sim_topk_tma<<<dim3(BATCH/QTILE, SPLITS), 256, SIM_DSMEM>>>(tmQ, tmM);

    // 3) exact fp32 rescore of candidates
    rescore_kernel<<<BATCH, 256>>>(query, memory);

    // 4) exact top-10
    merge_topk_kernel<<<BATCH/8, 256>>>();

    // 5) q projection: qp = query @ w_q^T + b_q
    gemm_nt128<<<dim3(8, 16, 1), 256>>>(query, EMB, 0, w_q, 0, b_q, 0,
                                        qp, EMB, 0, EMB);

    // 6) T[b,h,:] = qp_h @ w_k_h   (absorbs k-projection)
    gemm_nn128_T<<<dim3(8, 16, 8), 256>>>(qp, w_k, T);

    // 7) attention: scores, softmax, weighted memory sum
    attention2<<<BATCH, 256>>>(memory, b_k);

    // 8) ctx_h = wm_h @ w_v_h^T + b_v_h   (absorbs v-projection)
    gemm_nt128<<<dim3(1, 16, 8), 256>>>(wm, HEADS*EMB, EMB,
                                        w_v, (long)HDIM*EMB,
                                        b_v, HDIM,
                                        ctx, EMB, HDIM, EMB);

    // 9) out = ctx @ w_o^T + b_o
    gemm_nt128<<<dim3(8, 16, 1), 256>>>(ctx, EMB, 0, w_o, 0, b_o, 0,
                                        out, EMB, 0, EMB);
}

// round 7
// speedup vs baseline: 13.7105x; 1.3220x over previous
#include <cuda_runtime.h>
#include <cuda.h>
#include <cuda_bf16.h>
#include <math.h>
#include <stdint.h>

#define BATCH   2048
#define EMB     1024
#define MSIZE   100000
#define HEADS   8
#define HDIM    128
#define TOPK    10
#define SPLITS  9
#define SPLIT_SZ 11136          // 87 m-blocks of 128; 9*11136 = 100224 >= 100000
#define CAND    (SPLITS*TOPK)   // 90 candidates per query

// ---- sim kernel geometry (TMA + mma.sync) ----
#define QTILE   128
#define MTILE   128
#define KCH     64                       // 64 bf16 = 128 B = SW128 atom row
#define NKC     (EMB/KCH)                // 16 chunks per m-block
#define NMB     (SPLIT_SZ/MTILE)         // 87 m-blocks per split
#define NCHUNK  (NMB*NKC)                // 1392
#define NSTAGE  4
#define A_BYTES (QTILE*128)              // 16384
#define B_BYTES (MTILE*128)              // 16384
#define STAGE_BYTES (A_BYTES+B_BYTES)    // 32768
#define CS_OFF  (NSTAGE*STAGE_BYTES)     // 131072
#define CS_STRIDE 132
#define SIM_DSMEM (CS_OFF + QTILE*CS_STRIDE*4)   // 198656

// ---------------- device scratch ----------------
__device__ __nv_bfloat16 g_mem_bf[MSIZE*EMB];   // 200 MB
__device__ __nv_bfloat16 g_q_bf  [BATCH*EMB];   // 4 MB
__device__ float g_qp [BATCH*EMB];
__device__ float g_T  [BATCH*HEADS*EMB];
__device__ float g_wm [BATCH*HEADS*EMB];
__device__ float g_ctx[BATCH*EMB];
__device__ float g_wkT[HEADS*EMB*HDIM];         // 4 MB transposed w_k
__device__ float g_zero[EMB];                   // zero-initialized bias
__device__ float g_cand_s[BATCH*CAND];
__device__ int   g_cand_i[BATCH*CAND];
__device__ int   g_topk [BATCH*TOPK];

// =====================================================================
// PTX helpers (sm_90-era only: TMA, mbarrier, ldmatrix, mma.sync)
// =====================================================================
__device__ __forceinline__ unsigned sm2u32(const void* p) {
    unsigned a;
    asm("{ .reg .u64 t; cvta.to.shared.u64 t, %1; cvt.u32.u64 %0, t; }"
        : "=r"(a) : "l"(p));
    return a;
}
#define MBAR_INIT(a, n) \
    asm volatile("mbarrier.init.shared.b64 [%0], %1;" :: "r"(a), "r"(n) : "memory")
#define MBAR_EXPECT_TX(a, n) \
    asm volatile("mbarrier.arrive.expect_tx.shared.b64 _, [%0], %1;" :: "r"(a), "r"(n) : "memory")
#define MBAR_ARRIVE(a) \
    asm volatile("mbarrier.arrive.shared.b64 _, [%0];" :: "r"(a) : "memory")
#define MBAR_WAIT(a, ph) do {                                             \
    asm volatile(                                                         \
        "{\n\t.reg .pred P1;\n\t"                                         \
        "W%=:\n\t"                                                        \
        "mbarrier.try_wait.parity.acquire.cta.shared::cta.b64 P1, [%0], %1, 0x989680;\n\t" \
        "@P1 bra.uni D%=;\n\t"                                            \
        "bra.uni W%=;\n\t"                                                \
        "D%=:\n\t}"                                                       \
        :: "r"(a), "r"(ph) : "memory");                                   \
} while (0)

#define TMA2D(dst, map, cx, cy, mbar) \
    asm volatile( \
        "cp.async.bulk.tensor.2d.shared::cta.global.tile.mbarrier::complete_tx::bytes " \
        "[%0], [%1, {%2, %3}], [%4];" \
        :: "r"(dst), "l"(map), "r"(cx), "r"(cy), "r"(mbar) : "memory")

__device__ __forceinline__ void ldsm4(unsigned &r0, unsigned &r1,
                                      unsigned &r2, unsigned &r3, unsigned addr)
{
    asm volatile("ldmatrix.sync.aligned.m8n8.x4.shared.b16 {%0,%1,%2,%3}, [%4];"
                 : "=r"(r0), "=r"(r1), "=r"(r2), "=r"(r3) : "r"(addr));
}
__device__ __forceinline__ void mma_bf16(float* c,
    unsigned a0, unsigned a1, unsigned a2, unsigned a3,
    unsigned b0, unsigned b1)
{
    asm volatile(
        "mma.sync.aligned.m16n8k16.row.col.f32.bf16.bf16.f32 "
        "{%0,%1,%2,%3}, {%4,%5,%6,%7}, {%8,%9}, {%0,%1,%2,%3};"
        : "+f"(c[0]), "+f"(c[1]), "+f"(c[2]), "+f"(c[3])
        : "r"(a0), "r"(a1), "r"(a2), "r"(a3), "r"(b0), "r"(b1));
}

// =====================================================================
// fp32 -> bf16 conversion (vectorized x4)
// =====================================================================
__global__ void to_bf16_kernel(const float* __restrict__ src,
                               __nv_bfloat16* __restrict__ dst, int n4)
{
    int i = blockIdx.x * blockDim.x + threadIdx.x;
    if (i >= n4) return;
    float4 v = ((const float4*)src)[i];
    __nv_bfloat16 o[4];
    o[0] = __float2bfloat16(v.x); o[1] = __float2bfloat16(v.y);
    o[2] = __float2bfloat16(v.z); o[3] = __float2bfloat16(v.w);
    ((uint2*)dst)[i] = *(uint2*)o;
}

// =====================================================================
// w_k transpose: wkT[h][e][k] = w_k[h*128+k][e]
// block (32,8), grid (EMB/32, HDIM/32, HEADS)
// =====================================================================
__global__ void transpose_wk(const float* __restrict__ wk,
                             float* __restrict__ wkT)
{
    __shared__ float tile[32][33];
    const int h  = blockIdx.z;
    const int e0 = blockIdx.x * 32;
    const int k0 = blockIdx.y * 32;
    const int tx = threadIdx.x, ty = threadIdx.y;

    #pragma unroll
    for (int i = 0; i < 4; i++)
        tile[ty + i * 8][tx] = wk[(size_t)(h * HDIM + k0 + ty + i * 8) * EMB + e0 + tx];
    __syncthreads();
    #pragma unroll
    for (int i = 0; i < 4; i++)
        wkT[(size_t)h * EMB * HDIM + (size_t)(e0 + ty + i * 8) * HDIM + k0 + tx] =
            tile[tx][ty + i * 8];
}

// =====================================================================
// Kernel 1: coarse sim = Qbf16 @ Membf16^T, TMA(SW128)-fed mma.sync,
// fused per-split top-10 candidate generation.
// grid = (BATCH/128, SPLITS) = (16, 9) = 144 CTAs (one full wave)
// =====================================================================
__global__ __launch_bounds__(256, 1) void sim_topk_tma(
    const __grid_constant__ CUtensorMap tmQ,
    const __grid_constant__ CUtensorMap tmM)
{
    extern __shared__ __align__(1024) char dsm[];
    __shared__ __align__(8) unsigned long long mbar[8];  // [0..3] full, [4..7] empty
    __shared__ float Ls[QTILE][TOPK];
    __shared__ int   Li[QTILE][TOPK];

    const int t    = threadIdx.x;
    const int lane = t & 31;
    const int warp = t >> 5;
    const int wq   = warp >> 2;
    const int wm   = warp & 3;
    const int qbase  = blockIdx.x * QTILE;
    const int mstart = blockIdx.y * SPLIT_SZ;

    const unsigned sb  = sm2u32(dsm);
    const unsigned mb0 = sm2u32(&mbar[0]);
    float* Cs = (float*)(dsm + CS_OFF);

    if (t == 0) {
        #pragma unroll
        for (int i = 0; i < 4; i++) MBAR_INIT(mb0 + i * 8, 1);
        #pragma unroll
        for (int i = 4; i < 8; i++) MBAR_INIT(mb0 + i * 8, 256);
    }
    if (t < QTILE) {
        #pragma unroll
        for (int i = 0; i < TOPK; i++) { Ls[t][i] = -1e30f; Li[t][i] = 0; }
    }
    __syncthreads();

    if (t == 0) {
        #pragma unroll
        for (int g = 0; g < 4; g++) {
            unsigned fb = mb0 + g * 8;
            MBAR_EXPECT_TX(fb, STAGE_BYTES);
            TMA2D(sb + g * STAGE_BYTES,           &tmQ, (g & 15) * KCH, qbase, fb);
            TMA2D(sb + g * STAGE_BYTES + A_BYTES, &tmM, (g & 15) * KCH,
                  mstart + (g >> 4) * MTILE, fb);
        }
    }

    const int xm  = lane & 7;
    const int ahi = lane >> 4;
    const int mi  = lane >> 3;
    const int blo = mi & 1;
    unsigned aRow[4], bRow[2];
    #pragma unroll
    for (int t4 = 0; t4 < 4; t4++)
        aRow[t4] = (unsigned)((wq * 64 + t4 * 16 + (lane & 15)) * 128);
    #pragma unroll
    for (int p = 0; p < 2; p++)
        bRow[p] = (unsigned)((wm * 32 + p * 16 + ((mi >> 1) * 8) + (lane & 7)) * 128)
                  + (unsigned)A_BYTES;

    for (int mbi = 0; mbi < NMB; mbi++) {
        float c[4][4][4];
        #pragma unroll
        for (int i = 0; i < 4; i++)
            #pragma unroll
            for (int j = 0; j < 4; j++)
                #pragma unroll
                for (int k = 0; k < 4; k++) c[i][j][k] = 0.f;

        for (int kc = 0; kc < NKC; kc++) {
            const int g = mbi * NKC + kc;
            const int s = g & 3;
            const unsigned stg = sb + (unsigned)s * STAGE_BYTES;

            MBAR_WAIT(mb0 + s * 8, (g >> 2) & 1);

            #pragma unroll
            for (int kk = 0; kk < 4; kk++) {
                unsigned b[4][2];
                {
                    const unsigned cB = (unsigned)((((kk << 1) | blo) ^ xm) << 4);
                    unsigned r0, r1, r2, r3;
                    ldsm4(r0, r1, r2, r3, stg + bRow[0] + cB);
                    b[0][0] = r0; b[0][1] = r1; b[1][0] = r2; b[1][1] = r3;
                    ldsm4(r0, r1, r2, r3, stg + bRow[1] + cB);
                    b[2][0] = r0; b[2][1] = r1; b[3][0] = r2; b[3][1] = r3;
                }
                const unsigned cA = (unsigned)((((kk << 1) | ahi) ^ xm) << 4);
                #pragma unroll
                for (int t4 = 0; t4 < 4; t4++) {
                    unsigned a0, a1, a2, a3;
                    ldsm4(a0, a1, a2, a3, stg + aRow[t4] + cA);
                    #pragma unroll
                    for (int bn = 0; bn < 4; bn++)
                        mma_bf16(c[t4][bn], a0, a1, a2, a3, b[bn][0], b[bn][1]);
                }
            }

            MBAR_ARRIVE(mb0 + 32 + s * 8);

            if (t == 0) {
                const int g2 = g + 4;
                if (g2 < NCHUNK) {
                    MBAR_WAIT(mb0 + 32 + s * 8, (g >> 2) & 1);
                    unsigned fb = mb0 + s * 8;
                    MBAR_EXPECT_TX(fb, STAGE_BYTES);
                    const int kc2 = g2 & 15, mb2 = g2 >> 4;
                    TMA2D(sb + s * STAGE_BYTES,           &tmQ, kc2 * KCH, qbase, fb);
                    TMA2D(sb + s * STAGE_BYTES + A_BYTES, &tmM, kc2 * KCH,
                          mstart + mb2 * MTILE, fb);
                }
            }
        }

        #pragma unroll
        for (int t4 = 0; t4 < 4; t4++)
            #pragma unroll
            for (int bn = 0; bn < 4; bn++) {
                int r0 = wq * 64 + t4 * 16 + (lane >> 2);
                int c0 = wm * 32 + bn * 8 + (lane & 3) * 2;
                Cs[r0 * CS_STRIDE + c0]           = c[t4][bn][0];
                Cs[r0 * CS_STRIDE + c0 + 1]       = c[t4][bn][1];
                Cs[(r0 + 8) * CS_STRIDE + c0]     = c[t4][bn][2];
                Cs[(r0 + 8) * CS_STRIDE + c0 + 1] = c[t4][bn][3];
            }
        __syncthreads();

        const int mb_base = mstart + mbi * MTILE;
        if (t < QTILE) {
            int nv = MSIZE - mb_base;
            if (nv > MTILE) nv = MTILE;
            for (int j = 0; j < nv; j++) {
                float s = Cs[t * CS_STRIDE + j];
                if (s > Ls[t][TOPK - 1]) {
                    int p = TOPK - 1;
                    while (p > 0 && Ls[t][p - 1] < s) {
                        Ls[t][p] = Ls[t][p - 1];
                        Li[t][p] = Li[t][p - 1];
                        p--;
                    }
                    Ls[t][p] = s;
                    Li[t][p] = mb_base + j;
                }
            }
        }
        __syncthreads();
    }

    if (t < QTILE) {
        int q = qbase + t;
        #pragma unroll
        for (int i = 0; i < TOPK; i++)
            g_cand_i[(size_t)q * CAND + blockIdx.y * TOPK + i] = Li[t][i];
    }
}

// =====================================================================
// Kernel 2: EXACT fp32 rescore of the 90 candidates per query.
// =====================================================================
__global__ void rescore_kernel(const float* __restrict__ query,
                               const float* __restrict__ memory)
{
    __shared__ float qs[EMB];
    const int b    = blockIdx.x;
    const int t    = threadIdx.x;
    const int lane = t & 31;
    const int warp = t >> 5;

    for (int i = t; i < EMB / 4; i += 256)
        *(float4*)&qs[i * 4] = *(const float4*)&query[(size_t)b * EMB + i * 4];
    __syncthreads();

    for (int ci = warp; ci < CAND; ci += 8) {
        int midx = g_cand_i[(size_t)b * CAND + ci];
        const float* m = memory + (size_t)midx * EMB;
        float p = 0.f;
        #pragma unroll
        for (int i = 0; i < EMB / 128; i++) {
            float4 mv = *(const float4*)&m[(lane + i * 32) * 4];
            float4 qv = *(const float4*)&qs[(lane + i * 32) * 4];
            p = fmaf(qv.x, mv.x, p);
            p = fmaf(qv.y, mv.y, p);
            p = fmaf(qv.z, mv.z, p);
            p = fmaf(qv.w, mv.w, p);
        }
        #pragma unroll
        for (int off = 16; off > 0; off >>= 1)
            p += __shfl_xor_sync(0xffffffffu, p, off);
        if (lane == 0) g_cand_s[(size_t)b * CAND + ci] = p;
    }
}

// =====================================================================
// Kernel 3: exact top-10 of the 90 exact scores (1 warp/query)
// =====================================================================
__global__ void merge_topk_kernel()
{
    int gw   = (blockIdx.x * blockDim.x + threadIdx.x) >> 5;
    int lane = threadIdx.x & 31;
    if (gw >= BATCH) return;

    float s[3]; int id[3];
    #pragma unroll
    for (int l = 0; l < 3; l++) {
        int ci = lane + l * 32;
        if (ci < CAND) {
            s[l]  = g_cand_s[(size_t)gw * CAND + ci];
            id[l] = g_cand_i[(size_t)gw * CAND + ci];
        } else { s[l] = -1e30f; id[l] = 0x7fffffff; }
    }

    for (int sel = 0; sel < TOPK; sel++) {
        float bs = -1e30f; int bi = 0x7fffffff;
        #pragma unroll
        for (int l = 0; l < 3; l++)
            if (s[l] > bs || (s[l] == bs && id[l] < bi)) { bs = s[l]; bi = id[l]; }
        #pragma unroll
        for (int off = 16; off > 0; off >>= 1) {
            float os = __shfl_down_sync(0xffffffffu, bs, off);
            int   oi = __shfl_down_sync(0xffffffffu, bi, off);
            if (os > bs || (os == bs && oi < bi)) { bs = os; bi = oi; }
        }
        bi = __shfl_sync(0xffffffffu, bi, 0);
        if (lane == 0) g_topk[gw * TOPK + sel] = bi;
        #pragma unroll
        for (int l = 0; l < 3; l++)
            if (id[l] == bi) s[l] = -1e30f;
    }
}

// =====================================================================
// Kernel 4: split-bf16 tensor NT GEMM  C = A @ B^T + bias
// A [M,K] fp32 (row stride lda, head stride hsA)
// B [N,K] fp32 (row stride = K, head stride hsB)
// In-flight split: x = hi + lo (bf16 each); C += Ah*Bh + Ah*Bl + Al*Bh.
// CTA tile 128x128, k-chunk 32, 8 warps (2x4), warp tile 64x32.
// grid = (N/128, M/128, heads)
// =====================================================================
#define G3_AH 0
#define G3_AL 10240
#define G3_BH 20480
#define G3_BL 30720
__global__ __launch_bounds__(256) void gemm3_nt(
    const float* __restrict__ A, int lda, long hsA,
    const float* __restrict__ B, long hsB,
    const float* __restrict__ bias, int hsBias,
    float* __restrict__ C, int ldc, long hsC, int K)
{
    __shared__ __align__(16) char sm[40960];

    const float* Az = A + (size_t)blockIdx.z * hsA;
    const float* Bz = B + (size_t)blockIdx.z * hsB;
    const float* bz = bias + (size_t)blockIdx.z * hsBias;
    float*       Cz = C + (size_t)blockIdx.z * hsC;

    const int t    = threadIdx.x;
    const int lane = t & 31;
    const int warp = t >> 5;
    const int wq   = warp >> 2;
    const int wm   = warp & 3;
    const int rbase = blockIdx.y * 128;
    const int cbase = blockIdx.x * 128;

    const unsigned sb = sm2u32(sm);
    const int mi = lane >> 3;
    // 40-bf16 (80 B) row stride: conflict-free ldmatrix (validated R2)
    const unsigned aOff = (unsigned)((wq * 64 + (lane & 15)) * 80 + (lane >> 4) * 16);
    unsigned bOff[2];
    #pragma unroll
    for (int p = 0; p < 2; p++)
        bOff[p] = (unsigned)((wm * 32 + p * 16 + ((mi >> 1) * 8) + (lane & 7)) * 80
                             + (mi & 1) * 16);

    float c[4][4][4];
    #pragma unroll
    for (int i = 0; i < 4; i++)
        #pragma unroll
        for (int j = 0; j < 4; j++)
            #pragma unroll
            for (int k = 0; k < 4; k++) c[i][j][k] = 0.f;

    for (int kb = 0; kb < K; kb += 32) {
        // ---- stage + split: 128 rows x 32 k each of A and B ----
        #pragma unroll
        for (int i = 0; i < 4; i++) {
            int s2  = t + i * 256;
            int row = s2 >> 3, kseg = s2 & 7;
            float4 va = *(const float4*)&Az[(size_t)(rbase + row) * lda + kb + kseg * 4];
            float4 vb = *(const float4*)&Bz[(size_t)(cbase + row) * K   + kb + kseg * 4];
            const float* pa = &va.x; const float* pb = &vb.x;
            __nv_bfloat16 ah[4], al[4], bh[4], bl[4];
            #pragma unroll
            for (int j = 0; j < 4; j++) {
                ah[j] = __float2bfloat16(pa[j]);
                al[j] = __float2bfloat16(pa[j] - __bfloat162float(ah[j]));
                bh[j] = __float2bfloat16(pb[j]);
                bl[j] = __float2bfloat16(pb[j] - __bfloat162float(bh[j]));
            }
            unsigned off = (unsigned)(row * 80 + kseg * 8);
            *(uint2*)(sm + G3_AH + off) = *(uint2*)ah;
            *(uint2*)(sm + G3_AL + off) = *(uint2*)al;
            *(uint2*)(sm + G3_BH + off) = *(uint2*)bh;
            *(uint2*)(sm + G3_BL + off) = *(uint2*)bl;
        }
        __syncthreads();

        #pragma unroll
        for (int kk = 0; kk < 2; kk++) {
            const unsigned ko = (unsigned)kk * 32;
            unsigned bh[4][2], bl[4][2];
            #pragma unroll
            for (int p = 0; p < 2; p++) {
                unsigned r0, r1, r2, r3;
                ldsm4(r0, r1, r2, r3, sb + G3_BH + bOff[p] + ko);
                bh[p*2][0] = r0; bh[p*2][1] = r1; bh[p*2+1][0] = r2; bh[p*2+1][1] = r3;
                ldsm4(r0, r1, r2, r3, sb + G3_BL + bOff[p] + ko);
                bl[p*2][0] = r0; bl[p*2][1] = r1; bl[p*2+1][0] = r2; bl[p*2+1][1] = r3;
            }
            #pragma unroll
            for (int t4 = 0; t4 < 4; t4++) {
                unsigned ah0, ah1, ah2, ah3, al0, al1, al2, al3;
                ldsm4(ah0, ah1, ah2, ah3, sb + G3_AH + aOff + t4 * (16 * 80) + ko);
                ldsm4(al0, al1, al2, al3, sb + G3_AL + aOff + t4 * (16 * 80) + ko);
                #pragma unroll
                for (int bn = 0; bn < 4; bn++) {
                    mma_bf16(c[t4][bn], ah0, ah1, ah2, ah3, bh[bn][0], bh[bn][1]);
                    mma_bf16(c[t4][bn], ah0, ah1, ah2, ah3, bl[bn][0], bl[bn][1]);
                    mma_bf16(c[t4][bn], al0, al1, al2, al3, bh[bn][0], bh[bn][1]);
                }
            }
        }
        __syncthreads();
    }

    #pragma unroll
    for (int t4 = 0; t4 < 4; t4++)
        #pragma unroll
        for (int bn = 0; bn < 4; bn++) {
            int r0 = rbase + wq * 64 + t4 * 16 + (lane >> 2);
            int c0 = cbase + wm * 32 + bn * 8 + (lane & 3) * 2;
            Cz[(size_t)r0 * ldc + c0]           = c[t4][bn][0] + bz[c0];
            Cz[(size_t)r0 * ldc + c0 + 1]       = c[t4][bn][1] + bz[c0 + 1];
            Cz[(size_t)(r0 + 8) * ldc + c0]     = c[t4][bn][2] + bz[c0];
            Cz[(size_t)(r0 + 8) * ldc + c0 + 1] = c[t4][bn][3] + bz[c0 + 1];
        }
}

// =====================================================================
// Kernel 5: attention. 1 CTA per batch row, 8 warps = 8 heads.
// =====================================================================
__global__ void attention2(const float* __restrict__ mem,
                           const float* __restrict__ b_k)
{
    __shared__ float Ms[TOPK][EMB];
    __shared__ int   idxs[TOPK];

    const int b = blockIdx.x;
    const int t = threadIdx.x;
    const int lane = t & 31;
    const int h = t >> 5;

    if (t < TOPK) idxs[t] = g_topk[b * TOPK + t];
    __syncthreads();

    for (int i = t; i < TOPK * (EMB / 4); i += 256) {
        int k  = i >> 8;
        int e4 = i & 255;
        *(float4*)&Ms[k][e4 * 4] =
            *(const float4*)&mem[(size_t)idxs[k] * EMB + e4 * 4];
    }
    __syncthreads();

    float Tr[32];
    const float* Tp = g_T + (size_t)b * HEADS * EMB + h * EMB;
    #pragma unroll
    for (int i = 0; i < 32; i++) Tr[i] = Tp[lane + i * 32];

    float cb = 0.f;
    const float* qpp = g_qp + (size_t)b * EMB + h * HDIM;
    const float* bkp = b_k + h * HDIM;
    #pragma unroll
    for (int j = 0; j < 4; j++) cb = fmaf(qpp[lane*4+j], bkp[lane*4+j], cb);
    #pragma unroll
    for (int off = 16; off > 0; off >>= 1)
        cb += __shfl_xor_sync(0xffffffffu, cb, off);

    const float scale = 0.08838834764831845f;  // 1/sqrt(128)
    float sc[TOPK];
    #pragma unroll
    for (int k = 0; k < TOPK; k++) {
        float p = 0.f;
        #pragma unroll
        for (int i = 0; i < 32; i++) p = fmaf(Tr[i], Ms[k][lane + i * 32], p);
        #pragma unroll
        for (int off = 16; off > 0; off >>= 1)
            p += __shfl_xor_sync(0xffffffffu, p, off);
        sc[k] = (p + cb) * scale;
    }

    float mx = sc[0];
    #pragma unroll
    for (int k = 1; k < TOPK; k++) mx = fmaxf(mx, sc[k]);
    float w[TOPK], sum = 0.f;
    #pragma unroll
    for (int k = 0; k < TOPK; k++) { w[k] = expf(sc[k] - mx); sum += w[k]; }
    float inv = 1.f / sum;
    #pragma unroll
    for (int k = 0; k < TOPK; k++) w[k] *= inv;

    float* wmp = g_wm + (size_t)b * HEADS * EMB + h * EMB;
    #pragma unroll
    for (int i = 0; i < 32; i++) {
        int e = lane + i * 32;
        float a = 0.f;
        #pragma unroll
        for (int k = 0; k < TOPK; k++) a = fmaf(w[k], Ms[k][e], a);
        wmp[e] = a;
    }
}

// =====================================================================
// host: tensormap encode via runtime-resolved driver entry point
// =====================================================================
typedef CUresult (*encode_fn_t)(
    CUtensorMap*, CUtensorMapDataType, cuuint32_t, void*,
    const cuuint64_t*, const cuuint64_t*, const cuuint32_t*, const cuuint32_t*,
    CUtensorMapInterleave, CUtensorMapSwizzle, CUtensorMapL2promotion,
    CUtensorMapFloatOOBfill);

static void encode_2d_bf16(encode_fn_t enc, CUtensorMap* tm, void* base,
                           uint64_t rows, uint32_t box_rows)
{
    cuuint64_t dims[2]    = {EMB, rows};
    cuuint64_t strides[1] = {EMB * 2};
    cuuint32_t box[2]     = {KCH, box_rows};
    cuuint32_t es[2]      = {1, 1};
    enc(tm, CU_TENSOR_MAP_DATA_TYPE_BFLOAT16, 2, base, dims, strides, box, es,
        CU_TENSOR_MAP_INTERLEAVE_NONE, CU_TENSOR_MAP_SWIZZLE_128B,
        CU_TENSOR_MAP_L2_PROMOTION_L2_128B, CU_TENSOR_MAP_FLOAT_OOB_FILL_NONE);
}

// =====================================================================
extern "C" void kernel_launch(void* const* d_in, const int* in_sizes, int n_in,
                              void* d_out, int out_size)
{
    const float* query  = (const float*)d_in[0];
    const float* memory = (const float*)d_in[1];
    const float* w_q    = (const float*)d_in[2];
    const float* w_k    = (const float*)d_in[3];
    const float* w_v    = (const float*)d_in[4];
    const float* b_q    = (const float*)d_in[5];
    const float* b_k    = (const float*)d_in[6];
    const float* b_v    = (const float*)d_in[7];
    const float* w_o    = (const float*)d_in[8];
    const float* b_o    = (const float*)d_in[9];
    float* out = (float*)d_out;

    __nv_bfloat16 *mbf, *qbf;
    float *qp, *T, *wm, *ctx, *wkT, *zero;
    cudaGetSymbolAddress((void**)&mbf,  g_mem_bf);
    cudaGetSymbolAddress((void**)&qbf,  g_q_bf);
    cudaGetSymbolAddress((void**)&qp,   g_qp);
    cudaGetSymbolAddress((void**)&T,    g_T);
    cudaGetSymbolAddress((void**)&wm,   g_wm);
    cudaGetSymbolAddress((void**)&ctx,  g_ctx);
    cudaGetSymbolAddress((void**)&wkT,  g_wkT);
    cudaGetSymbolAddress((void**)&zero, g_zero);

    encode_fn_t enc = nullptr;
    cudaDriverEntryPointQueryResult qr;
    cudaGetDriverEntryPointByVersion("cuTensorMapEncodeTiled", (void**)&enc,
                                     12000, cudaEnableDefault, &qr);
    CUtensorMap tmQ, tmM;
    encode_2d_bf16(enc, &tmQ, qbf, BATCH, QTILE);
    encode_2d_bf16(enc, &tmM, mbf, MSIZE, MTILE);

    cudaFuncSetAttribute(sim_topk_tma,
                         cudaFuncAttributeMaxDynamicSharedMemorySize, SIM_DSMEM);

    // 1) bf16 conversions + w_k transpose
    to_bf16_kernel<<<(MSIZE*EMB/4 + 255)/256, 256>>>(memory, mbf, MSIZE*EMB/4);
    to_bf16_kernel<<<(BATCH*EMB/4 + 255)/256, 256>>>(query,  qbf, BATCH*EMB/4);
    transpose_wk<<<dim3(EMB/32, HDIM/32, HEADS), dim3(32, 8)>>>(w_k, wkT);

    // 2) TMA+mma.sync coarse similarity -> 90 candidates/query
    sim_topk_tma<<<dim3(BATCH/QTILE, SPLITS), 256, SIM_DSMEM>>>(tmQ, tmM);

    // 3) exact fp32 rescore of candidates
    rescore_kernel<<<BATCH, 256>>>(query, memory);

    // 4) exact top-10
    merge_topk_kernel<<<BATCH/8, 256>>>();

    // 5) qp = query @ w_q^T + b_q        (split-bf16 tensor GEMM)
    gemm3_nt<<<dim3(8, 16, 1), 256>>>(query, EMB, 0, w_q, 0, b_q, 0,
                                      qp, EMB, 0, EMB);

    // 6) T[b,h,:] = qp_h @ wkT_h^T       (absorbs k-projection)
    gemm3_nt<<<dim3(8, 16, 8), 256>>>(qp, EMB, HDIM, wkT, (long)EMB*HDIM,
                                      zero, 0, T, HEADS*EMB, EMB, HDIM);

    // 7) attention: scores, softmax, weighted memory sum
    attention2<<<BATCH, 256>>>(memory, b_k);

    // 8) ctx_h = wm_h @ w_v_h^T + b_v_h  (absorbs v-projection)
    gemm3_nt<<<dim3(1, 16, 8), 256>>>(wm, HEADS*EMB, EMB, w_v, (long)HDIM*EMB,
                                      b_v, HDIM, ctx, EMB, HDIM, EMB);

    // 9) out = ctx @ w_o^T + b_o
    gemm3_nt<<<dim3(8, 16, 1), 256>>>(ctx, EMB, 0, w_o, 0, b_o, 0,
                                      out, EMB, 0, EMB);
}